// round 8
// baseline (speedup 1.0000x reference)
#include <cuda_runtime.h>
#include <cuda_fp16.h>
#include <math.h>
#include <stdint.h>

#define BB 4
#define CC 64
#define NN 4096
#define RR 4
#define EPSF 1e-6f
#define FSCALE 0.18033688011112042f   // 0.125 * log2(e), folded into Q

// ---------------- helpers ----------------
__device__ __forceinline__ uint32_t smem_u32(const void* p) {
    uint32_t a;
    asm("{ .reg .u64 t; cvta.to.shared.u64 t, %1; cvt.u32.u64 %0, t; }" : "=r"(a) : "l"(p));
    return a;
}
#define SWZ(off) ((off) ^ (((off) >> 3) & 0x70))   // SW128-style row swizzle

__device__ __forceinline__ void ldmx4(uint32_t* r, uint32_t addr) {
    asm volatile("ldmatrix.sync.aligned.m8n8.x4.shared.b16 {%0,%1,%2,%3}, [%4];"
        : "=r"(r[0]), "=r"(r[1]), "=r"(r[2]), "=r"(r[3]) : "r"(addr));
}
__device__ __forceinline__ void mma16816(float* d, const uint32_t* a,
                                         uint32_t b0, uint32_t b1) {
    asm volatile("mma.sync.aligned.m16n8k16.row.col.f32.f16.f16.f32 "
        "{%0,%1,%2,%3}, {%4,%5,%6,%7}, {%8,%9}, {%0,%1,%2,%3};"
        : "+f"(d[0]), "+f"(d[1]), "+f"(d[2]), "+f"(d[3])
        : "r"(a[0]), "r"(a[1]), "r"(a[2]), "r"(a[3]), "r"(b0), "r"(b1));
}
__device__ __forceinline__ uint32_t packh2(float lo, float hi) {  // lower=lo, upper=hi
    uint32_t r; asm("cvt.rn.f16x2.f32 %0, %1, %2;" : "=r"(r) : "f"(hi), "f"(lo)); return r;
}
#define CP_A16(dst, src) \
    asm volatile("cp.async.cg.shared.global [%0], [%1], 16;" :: "r"(dst), "l"(src) : "memory")
#define MBAR_INIT(mbar, count) \
    asm volatile("mbarrier.init.shared.b64 [%0], %1;" :: "r"((uint32_t)(mbar)), "r"((uint32_t)(count)) : "memory")
#define MBAR_ARRIVE(mbar) \
    asm volatile("mbarrier.arrive.shared.b64 _, [%0];" :: "r"((uint32_t)(mbar)) : "memory")
#define CPASYNC_MBAR_ARRIVE_NOINC(mbar) \
    asm volatile("cp.async.mbarrier.arrive.noinc.shared.b64 [%0];" :: "r"((uint32_t)(mbar)) : "memory")
#define MBAR_WAIT(mbar, parity) do { \
    uint32_t _m = (uint32_t)(mbar); uint32_t _p = (uint32_t)(parity); uint32_t _d; \
    asm volatile("{\n\t.reg .pred p;\n\tmbarrier.try_wait.parity.acquire.cta.shared::cta.b64 p, [%1], %2;\n\tselp.b32 %0, 1, 0, p;\n\t}" \
        : "=r"(_d) : "r"(_m), "r"(_p) : "memory"); \
    if (!_d) { \
        asm volatile("{\n\t.reg .pred P1;\n\tWL_%=:\n\tmbarrier.try_wait.parity.acquire.cta.shared::cta.b64 P1, [%0], %1, 0x989680;\n\t@P1 bra.uni WD_%=;\n\tbra.uni WL_%=;\n\tWD_%=:\n\t}" \
            :: "r"(_m), "r"(_p) : "memory"); \
    } } while(0)

// FMA-pipe exp2 (keeps exps OFF the MUFU pipe; rel err ~2e-6)
__device__ __forceinline__ float fexp2(float x) {
    const float MAGIC = 12582912.0f;          // 1.5 * 2^23
    x = fmaxf(x, -80.0f);
    float nf = x + MAGIC;
    float f  = x - (nf - MAGIC);              // f in [-0.5, 0.5]
    float p = 1.3333558146e-3f;
    p = fmaf(p, f, 9.6181298421e-3f);
    p = fmaf(p, f, 5.5504108665e-2f);
    p = fmaf(p, f, 2.4022650696e-1f);
    p = fmaf(p, f, 6.9314718056e-1f);
    p = fmaf(p, f, 1.0f);
    int r = __float_as_int(p) + (__float_as_int(nf) << 23);
    return __int_as_float(r);
}
__device__ __forceinline__ float fexp(float x) {   // e^x for sigmoids
    return fexp2(x * 1.4426950408889634f);
}

// ---------------- scratch (device globals) ----------------
__device__ float g_stat[BB][CC][6];
__device__ float g_se[BB][CC];
__device__ float g_W[5][BB][CC][CC];
__device__ float g_bias[5][BB][CC];
__device__ __half g_qh[2][BB][NN][CC];   // Q hi, per branch, [n][c], scaled by FSCALE
__device__ __half g_ql[2][BB][NN][CC];   // Q lo
__device__ __half g_k [2][BB][NN][CC];   // K single fp16, [n][c]
__device__ __half g_v [BB][CC][NN];      // V single fp16, [c][n]
__device__ float g_h[2][BB][CC][NN];     // attention outputs

// ================= kernel 1: per-(b,c) sums over HW =================
__global__ void k_stats(const float* __restrict__ x1, const float* __restrict__ x2) {
    int bc = blockIdx.x;
    const float* p1 = x1 + (size_t)bc * NN;
    const float* p2 = x2 + (size_t)bc * NN;
    float s1=0.f,q1=0.f,s2=0.f,q2=0.f,sx=0.f,qx=0.f;
    for (int i = threadIdx.x; i < NN; i += 256) {
        float a = p1[i], b_ = p2[i], s = a + b_;
        s1 += a; q1 += a*a; s2 += b_; q2 += b_*b_; sx += s; qx += s*s;
    }
    __shared__ float red[6][256];
    red[0][threadIdx.x]=s1; red[1][threadIdx.x]=q1; red[2][threadIdx.x]=s2;
    red[3][threadIdx.x]=q2; red[4][threadIdx.x]=sx; red[5][threadIdx.x]=qx;
    __syncthreads();
    for (int off=128; off>=1; off>>=1) {
        if (threadIdx.x < (unsigned)off) {
            #pragma unroll
            for (int k=0;k<6;k++) red[k][threadIdx.x] += red[k][threadIdx.x+off];
        }
        __syncthreads();
    }
    if (threadIdx.x < 6) g_stat[bc/CC][bc%CC][threadIdx.x] = red[threadIdx.x][0];
}

// ============ kernel 2: SE MLP + GroupNorm fold into weights ============
__global__ void k_prep(const float* __restrict__ se_w1, const float* __restrict__ se_w2,
                       const float* __restrict__ gamma, const float* __restrict__ beta,
                       const float* __restrict__ wq, const float* __restrict__ bq,
                       const float* __restrict__ wk, const float* __restrict__ bk,
                       const float* __restrict__ wv, const float* __restrict__ bv) {
    int b = blockIdx.x;
    int c = threadIdx.x;
    __shared__ float sy[CC], sh[RR], sA[3][CC], sBc[3][CC];
    float st[6], stp[6];
    #pragma unroll
    for (int k=0;k<6;k++) st[k] = g_stat[b][c][k];
    int cp = c ^ 1;
    #pragma unroll
    for (int k=0;k<6;k++) stp[k] = g_stat[b][cp][k];

    sy[c] = st[4] * (1.0f/NN);
    __syncthreads();
    if (c < RR) {
        float h = 0.f;
        for (int ci=0; ci<CC; ci++) h += se_w1[c*CC+ci]*sy[ci];
        sh[c] = fmaxf(h, 0.f);
    }
    __syncthreads();
    {
        float z = 0.f;
        #pragma unroll
        for (int r=0;r<RR;r++) z += se_w2[c*RR+r]*sh[r];
        g_se[b][c] = 1.f/(1.f+fexp(-z));
    }
    const float inv = 1.0f/(2.0f*NN);
    float ga = gamma[c], be = beta[c];
    #pragma unroll
    for (int t=0;t<3;t++) {
        float mean = (st[2*t]+stp[2*t])*inv;
        float var  = (st[2*t+1]+stp[2*t+1])*inv - mean*mean;
        float rs = rsqrtf(var + EPSF);
        float A = rs*ga;
        sA[t][c] = A;
        sBc[t][c] = be - mean*A;
    }
    __syncthreads();
    for (int p=0;p<5;p++) {
        const float* w  = (p==0||p==2)? wq : (p==1||p==3)? wk : wv;
        const float* bb = (p==0||p==2)? bq : (p==1||p==3)? bk : bv;
        int t = (p<2)?0 : (p<4)?1 : 2;
        float acc = bb[c];
        for (int ci=0; ci<CC; ci++) {
            float wvl = w[c*CC+ci];
            acc += wvl * sBc[t][ci];
            g_W[p][b][ci][c] = wvl * sA[t][ci];
        }
        g_bias[p][b][c] = acc;
    }
}

// ====== kernel 3: projections -> fp16 operand tensors ======
__global__ void __launch_bounds__(256) k_proj(const float* __restrict__ x1,
                                              const float* __restrict__ x2) {
    int nt = blockIdx.x, p = blockIdx.y, b = blockIdx.z;
    int n0 = nt * 64;
    __shared__ float xs[CC][64];
    __shared__ float Wt[CC][CC];
    __shared__ float bias[CC];
    int tid = threadIdx.x;
    const float* s1 = x1 + (size_t)b*CC*NN + n0;
    const float* s2 = x2 + (size_t)b*CC*NN + n0;
    for (int idx = tid; idx < CC*64; idx += 256) {
        int ci = idx >> 6, n = idx & 63;
        float v;
        if (p < 2)       v = s1[(size_t)ci*NN + n];
        else if (p < 4)  v = s2[(size_t)ci*NN + n];
        else             v = s1[(size_t)ci*NN + n] + s2[(size_t)ci*NN + n];
        xs[ci][n] = v;
    }
    for (int idx = tid; idx < CC*CC; idx += 256)
        (&Wt[0][0])[idx] = (&g_W[p][b][0][0])[idx];
    if (tid < CC) bias[tid] = g_bias[p][b][tid];
    __syncthreads();

    int cg = tid >> 4;
    int ng = tid & 15;
    float acc[4][4];
    #pragma unroll
    for (int i=0;i<4;i++){ float bv_ = bias[4*cg+i];
        #pragma unroll
        for (int j=0;j<4;j++) acc[i][j]=bv_; }
    for (int ci=0; ci<CC; ci++) {
        float4 w4 = *(const float4*)&Wt[ci][4*cg];
        float4 x4 = *(const float4*)&xs[ci][4*ng];
        float wa[4]={w4.x,w4.y,w4.z,w4.w};
        float xa[4]={x4.x,x4.y,x4.z,x4.w};
        #pragma unroll
        for (int i=0;i<4;i++)
            #pragma unroll
            for (int j=0;j<4;j++) acc[i][j] += wa[i]*xa[j];
    }
    if (p == 0 || p == 2) {
        int br = p >> 1;
        #pragma unroll
        for (int j=0;j<4;j++) {
            int n = n0 + 4*ng + j;
            float v0=acc[0][j]*FSCALE, v1=acc[1][j]*FSCALE;
            float v2=acc[2][j]*FSCALE, v3=acc[3][j]*FSCALE;
            uint32_t h01 = packh2(v0, v1), h23 = packh2(v2, v3);
            float r0 = __half2float(__ushort_as_half((unsigned short)(h01 & 0xffff)));
            float r1 = __half2float(__ushort_as_half((unsigned short)(h01 >> 16)));
            float r2 = __half2float(__ushort_as_half((unsigned short)(h23 & 0xffff)));
            float r3 = __half2float(__ushort_as_half((unsigned short)(h23 >> 16)));
            uint32_t l01 = packh2(v0 - r0, v1 - r1), l23 = packh2(v2 - r2, v3 - r3);
            *(uint2*)&g_qh[br][b][n][4*cg] = make_uint2(h01, h23);
            *(uint2*)&g_ql[br][b][n][4*cg] = make_uint2(l01, l23);
        }
    } else if (p == 1 || p == 3) {
        int br = p >> 1;
        #pragma unroll
        for (int j=0;j<4;j++) {
            int n = n0 + 4*ng + j;
            uint32_t h01 = packh2(acc[0][j], acc[1][j]);
            uint32_t h23 = packh2(acc[2][j], acc[3][j]);
            *(uint2*)&g_k[br][b][n][4*cg] = make_uint2(h01, h23);
        }
    } else {
        #pragma unroll
        for (int i=0;i<4;i++) {
            int c = 4*cg + i;
            uint32_t h01 = packh2(acc[i][0], acc[i][1]);
            uint32_t h23 = packh2(acc[i][2], acc[i][3]);
            *(uint2*)&g_v[b][c][n0 + 4*ng] = make_uint2(h01, h23);
        }
    }
}

// ============== kernel 4: warp-specialized mma.sync flash attention ==============
// 160 thr: warps 0-3 consume (16 q-rows each), warp 4 = cp.async producer.
// 3-stage K|V ring (16KB/stage) with full/empty mbarriers; consumers have NO
// block barrier in the mainloop, so softmax of one warp overlaps MMA of others.
#define STG   16384
#define BARS  49152                  // 3 stages end; full[0..2] then empty[0..2]
#define SMSZ  49280

__global__ void __launch_bounds__(160, 3) k_attn() {
    extern __shared__ __align__(128) char smem[];
    uint32_t sb = smem_u32(smem);
    int tid = threadIdx.x, l = tid & 31, w = tid >> 5;
    int qt = blockIdx.x;
    int bbi = blockIdx.y; int b = bbi >> 1, br = bbi & 1;

    const __half* QH = &g_qh[br][b][qt*64][0];
    const __half* QL = &g_ql[br][b][qt*64][0];
    const __half* K  = &g_k[br][b][0][0];
    const __half* V  = &g_v[b][0][0];

    if (tid == 0) {
        #pragma unroll
        for (int s = 0; s < 3; s++) {
            MBAR_INIT(sb + BARS + 8*s, 32);       // full: 32 producer lanes
            MBAR_INIT(sb + BARS + 24 + 8*s, 4);   // empty: 4 consumer warps
        }
    }
    // ---- Q staging in stage0 (hi) / stage0+8K (lo) ----
    if (tid < 128) {
        for (int u = tid; u < 512; u += 128) {
            int r = u >> 3, q = u & 7;
            uint32_t off = SWZ(r*128 + q*16);
            *(uint4*)(smem + off)        = ((const uint4*)(QH + r*64))[q];
            *(uint4*)(smem + 8192 + off) = ((const uint4*)(QL + r*64))[q];
        }
    }
    __syncthreads();
    uint32_t qh[4][4], ql[4][4];
    if (w < 4) {
        int arow = 16*w + ((l>>3)&1)*8 + (l&7);
        int acolh = ((l>>4)&1)*16;
        #pragma unroll
        for (int ks = 0; ks < 4; ks++) {
            uint32_t off = SWZ(arow*128 + ks*32 + acolh);
            ldmx4(qh[ks], sb + off);
            ldmx4(ql[ks], sb + 8192 + off);
        }
    }
    __syncthreads();   // Q consumed; stages free for the producer

    if (w == 4) {
        // ================= producer =================
        for (int t = 0; t < 64; t++) {
            int s = t % 3, wrap = t / 3;
            uint32_t fullb  = sb + BARS + 8*s;
            uint32_t emptyb = sb + BARS + 24 + 8*s;
            if (wrap > 0) MBAR_WAIT(emptyb, (wrap-1) & 1);
            uint32_t base = sb + s*STG;
            const __half* kg = K + (size_t)t*64*CC;
            const __half* vg = V + t*64;
            for (int u = l; u < 512; u += 32) {
                int r = u >> 3, q = u & 7;
                uint32_t off = SWZ(r*128 + q*16);
                CP_A16(base + off,        kg + r*64 + q*8);
                CP_A16(base + 8192 + off, vg + (size_t)r*NN + q*8);
            }
            CPASYNC_MBAR_ARRIVE_NOINC(fullb);
        }
    } else {
        // ================= consumers =================
        float o[8][4];
        #pragma unroll
        for (int u=0;u<8;u++) { o[u][0]=0.f; o[u][1]=0.f; o[u][2]=0.f; o[u][3]=0.f; }
        float ls0 = 0.f, ls1 = 0.f;
        int brow = ((l>>4)&1)*8 + (l&7);
        int bcolh = ((l>>3)&1)*16;

        for (int kt = 0; kt < 64; kt++) {
            int s = kt % 3, wrap = kt / 3;
            MBAR_WAIT(sb + BARS + 8*s, wrap & 1);
            uint32_t base = sb + s*STG;
            // ---- S = Qh*K + Ql*K ----
            float sc[8][4];
            #pragma unroll
            for (int u=0;u<8;u++) { sc[u][0]=0.f; sc[u][1]=0.f; sc[u][2]=0.f; sc[u][3]=0.f; }
            #pragma unroll
            for (int ks = 0; ks < 4; ks++) {
                #pragma unroll
                for (int up = 0; up < 4; up++) {
                    uint32_t kh[4];
                    ldmx4(kh, base + SWZ((16*up + brow)*128 + ks*32 + bcolh));
                    mma16816(sc[2*up],   qh[ks], kh[0], kh[1]);
                    mma16816(sc[2*up+1], qh[ks], kh[2], kh[3]);
                    mma16816(sc[2*up],   ql[ks], kh[0], kh[1]);
                    mma16816(sc[2*up+1], ql[ks], kh[2], kh[3]);
                }
            }
            // ---- softmax (exp2 domain) + fp16 hi/lo split of P ----
            uint32_t ph[8][2], pl[8][2];
            #pragma unroll
            for (int u = 0; u < 8; u++) {
                float p0 = fexp2(sc[u][0]), p1 = fexp2(sc[u][1]);
                float p2 = fexp2(sc[u][2]), p3 = fexp2(sc[u][3]);
                ls0 += p0 + p1; ls1 += p2 + p3;
                uint32_t hA = packh2(p0, p1), hB = packh2(p2, p3);
                float r0 = __half2float(__ushort_as_half((unsigned short)(hA & 0xffff)));
                float r1 = __half2float(__ushort_as_half((unsigned short)(hA >> 16)));
                float r2 = __half2float(__ushort_as_half((unsigned short)(hB & 0xffff)));
                float r3 = __half2float(__ushort_as_half((unsigned short)(hB >> 16)));
                ph[u][0] = hA; ph[u][1] = hB;
                pl[u][0] = packh2(p0 - r0, p1 - r1);
                pl[u][1] = packh2(p2 - r2, p3 - r3);
            }
            // ---- O += Ph*V + Pl*V ----
            #pragma unroll
            for (int t = 0; t < 4; t++) {
                uint32_t ah[4] = { ph[2*t][0], ph[2*t][1], ph[2*t+1][0], ph[2*t+1][1] };
                uint32_t al[4] = { pl[2*t][0], pl[2*t][1], pl[2*t+1][0], pl[2*t+1][1] };
                #pragma unroll
                for (int up = 0; up < 4; up++) {
                    uint32_t vh[4];
                    ldmx4(vh, base + 8192 + SWZ((16*up + brow)*128 + t*32 + bcolh));
                    mma16816(o[2*up],   ah, vh[0], vh[1]);
                    mma16816(o[2*up+1], ah, vh[2], vh[3]);
                    mma16816(o[2*up],   al, vh[0], vh[1]);
                    mma16816(o[2*up+1], al, vh[2], vh[3]);
                }
            }
            __syncwarp();
            if (l == 0) MBAR_ARRIVE(sb + BARS + 24 + 8*s);
        }
        // ---- row sums across quads, normalize (stash in o) ----
        ls0 += __shfl_xor_sync(0xffffffffu, ls0, 1);
        ls0 += __shfl_xor_sync(0xffffffffu, ls0, 2);
        ls1 += __shfl_xor_sync(0xffffffffu, ls1, 1);
        ls1 += __shfl_xor_sync(0xffffffffu, ls1, 2);
        float ri0 = 1.0f / ls0, ri1 = 1.0f / ls1;
        #pragma unroll
        for (int u=0;u<8;u++) { o[u][0]*=ri0; o[u][1]*=ri0; o[u][2]*=ri1; o[u][3]*=ri1; }
        __syncthreads();   // ring fully consumed; smem reusable for transpose
        float* W = (float*)smem + w * 1088;          // 64 rows x stride 17
        #pragma unroll
        for (int u = 0; u < 8; u++) {
            int c0 = 8*u + 2*(l&3);
            int r  = l >> 2;
            W[c0*17 + r]       = o[u][0];
            W[(c0+1)*17 + r]   = o[u][1];
            W[c0*17 + r + 8]   = o[u][2];
            W[(c0+1)*17 + r+8] = o[u][3];
        }
        __syncwarp();
        float* H = &g_h[br][b][0][0];
        int n0 = qt*64 + w*16;
        #pragma unroll
        for (int rep = 0; rep < 2; rep++) {
            int cc = 2*l + rep;
            #pragma unroll
            for (int k4 = 0; k4 < 4; k4++) {
                float4 v = make_float4(W[cc*17+4*k4], W[cc*17+4*k4+1],
                                       W[cc*17+4*k4+2], W[cc*17+4*k4+3]);
                *(float4*)&H[(size_t)cc*NN + n0 + 4*k4] = v;
            }
        }
    }
    if (w == 4) __syncthreads();     // producer joins the consumers' barrier
}

// ================= kernel 5: final combine =================
__global__ void k_final(const float* __restrict__ x1, const float* __restrict__ x2,
                        float* __restrict__ out) {
    int idx4 = blockIdx.x*256 + threadIdx.x;
    if (idx4 >= BB*CC*NN/4) return;
    int idx = idx4 * 4;
    int bc = idx >> 12;
    int b = bc >> 6, c = bc & 63;
    float se = g_se[b][c];
    float4 a1 = *(const float4*)&x1[idx];
    float4 a2 = *(const float4*)&x2[idx];
    float4 h1 = *(const float4*)(&g_h[0][0][0][0] + idx);
    float4 h2 = *(const float4*)(&g_h[1][0][0][0] + idx);
    float xs[4] = {a1.x+a2.x, a1.y+a2.y, a1.z+a2.z, a1.w+a2.w};
    float h1a[4]={h1.x,h1.y,h1.z,h1.w};
    float h2a[4]={h2.x,h2.y,h2.z,h2.w};
    float oa[4];
    #pragma unroll
    for (int k=0;k<4;k++) {
        float ww = 1.f/(1.f+fexp(-xs[k]*se));
        oa[k] = 2.f*h1a[k]*ww + 2.f*h2a[k]*(1.f-ww);
    }
    *(float4*)&out[idx] = make_float4(oa[0],oa[1],oa[2],oa[3]);
}

// ================= launcher =================
extern "C" void kernel_launch(void* const* d_in, const int* in_sizes, int n_in,
                              void* d_out, int out_size) {
    const float* x1    = (const float*)d_in[0];
    const float* x2    = (const float*)d_in[1];
    const float* se_w1 = (const float*)d_in[2];
    const float* se_w2 = (const float*)d_in[3];
    const float* gam   = (const float*)d_in[4];
    const float* bet   = (const float*)d_in[5];
    const float* wq    = (const float*)d_in[6];
    const float* bq    = (const float*)d_in[7];
    const float* wk    = (const float*)d_in[8];
    const float* bk    = (const float*)d_in[9];
    const float* wv    = (const float*)d_in[10];
    const float* bv    = (const float*)d_in[11];
    float* out = (float*)d_out;

    k_stats<<<BB*CC, 256>>>(x1, x2);
    k_prep<<<BB, CC>>>(se_w1, se_w2, gam, bet, wq, bq, wk, bk, wv, bv);
    k_proj<<<dim3(64, 5, BB), 256>>>(x1, x2);
    cudaFuncSetAttribute(k_attn, cudaFuncAttributeMaxDynamicSharedMemorySize, SMSZ);
    k_attn<<<dim3(64, 8), 160, SMSZ>>>();
    k_final<<<(BB*CC*NN/4 + 255)/256, 256>>>(x1, x2, out);
}

// round 11
// speedup vs baseline: 1.2502x; 1.2502x over previous
#include <cuda_runtime.h>
#include <cuda_fp16.h>
#include <math.h>
#include <stdint.h>

#define BB 4
#define CC 64
#define NN 4096
#define RR 4
#define EPSF 1e-6f
#define FSCALE 0.18033688011112042f   // 0.125 * log2(e), folded into Q

// ---------------- helpers ----------------
__device__ __forceinline__ uint32_t smem_u32(const void* p) {
    uint32_t a;
    asm("{ .reg .u64 t; cvta.to.shared.u64 t, %1; cvt.u32.u64 %0, t; }" : "=r"(a) : "l"(p));
    return a;
}
#define SWZ(off) ((off) ^ (((off) >> 3) & 0x70))   // SW128-style row swizzle

__device__ __forceinline__ void ldmx4(uint32_t* r, uint32_t addr) {
    asm volatile("ldmatrix.sync.aligned.m8n8.x4.shared.b16 {%0,%1,%2,%3}, [%4];"
        : "=r"(r[0]), "=r"(r[1]), "=r"(r[2]), "=r"(r[3]) : "r"(addr));
}
__device__ __forceinline__ void mma16816(float* d, const uint32_t* a,
                                         uint32_t b0, uint32_t b1) {
    asm volatile("mma.sync.aligned.m16n8k16.row.col.f32.f16.f16.f32 "
        "{%0,%1,%2,%3}, {%4,%5,%6,%7}, {%8,%9}, {%0,%1,%2,%3};"
        : "+f"(d[0]), "+f"(d[1]), "+f"(d[2]), "+f"(d[3])
        : "r"(a[0]), "r"(a[1]), "r"(a[2]), "r"(a[3]), "r"(b0), "r"(b1));
}
__device__ __forceinline__ uint32_t packh2(float lo, float hi) {  // lower=lo, upper=hi
    uint32_t r; asm("cvt.rn.f16x2.f32 %0, %1, %2;" : "=r"(r) : "f"(hi), "f"(lo)); return r;
}
#define CP_A16(dst, src) \
    asm volatile("cp.async.cg.shared.global [%0], [%1], 16;" :: "r"(dst), "l"(src) : "memory")
#define CP_COMMIT() asm volatile("cp.async.commit_group;" ::: "memory")
#define CP_WAIT(n)  asm volatile("cp.async.wait_group %0;" :: "n"(n) : "memory")

// FMA-pipe exp2 (keeps exps OFF the MUFU pipe; rel err ~2e-6)
__device__ __forceinline__ float fexp2(float x) {
    const float MAGIC = 12582912.0f;          // 1.5 * 2^23
    x = fmaxf(x, -80.0f);
    float nf = x + MAGIC;
    float f  = x - (nf - MAGIC);              // f in [-0.5, 0.5]
    float p = 1.3333558146e-3f;
    p = fmaf(p, f, 9.6181298421e-3f);
    p = fmaf(p, f, 5.5504108665e-2f);
    p = fmaf(p, f, 2.4022650696e-1f);
    p = fmaf(p, f, 6.9314718056e-1f);
    p = fmaf(p, f, 1.0f);
    int r = __float_as_int(p) + (__float_as_int(nf) << 23);
    return __int_as_float(r);
}
__device__ __forceinline__ float fexp(float x) {   // e^x for sigmoids
    return fexp2(x * 1.4426950408889634f);
}

// ---------------- scratch (device globals) ----------------
__device__ float g_stat[BB][CC][6];
__device__ float g_se[BB][CC];
__device__ float g_W[5][BB][CC][CC];
__device__ float g_bias[5][BB][CC];
__device__ __half g_qh[2][BB][NN][CC];   // Q hi, per branch, [n][c], scaled by FSCALE
__device__ __half g_ql[2][BB][NN][CC];   // Q lo
__device__ __half g_k [2][BB][NN][CC];   // K single fp16, [n][c]
__device__ __half g_v [BB][CC][NN];      // V single fp16, [c][n]
__device__ float g_h[2][BB][CC][NN];     // attention outputs

// ================= kernel 1: per-(b,c) sums over HW =================
__global__ void k_stats(const float* __restrict__ x1, const float* __restrict__ x2) {
    int bc = blockIdx.x;
    const float* p1 = x1 + (size_t)bc * NN;
    const float* p2 = x2 + (size_t)bc * NN;
    float s1=0.f,q1=0.f,s2=0.f,q2=0.f,sx=0.f,qx=0.f;
    for (int i = threadIdx.x; i < NN; i += 256) {
        float a = p1[i], b_ = p2[i], s = a + b_;
        s1 += a; q1 += a*a; s2 += b_; q2 += b_*b_; sx += s; qx += s*s;
    }
    __shared__ float red[6][256];
    red[0][threadIdx.x]=s1; red[1][threadIdx.x]=q1; red[2][threadIdx.x]=s2;
    red[3][threadIdx.x]=q2; red[4][threadIdx.x]=sx; red[5][threadIdx.x]=qx;
    __syncthreads();
    for (int off=128; off>=1; off>>=1) {
        if (threadIdx.x < (unsigned)off) {
            #pragma unroll
            for (int k=0;k<6;k++) red[k][threadIdx.x] += red[k][threadIdx.x+off];
        }
        __syncthreads();
    }
    if (threadIdx.x < 6) g_stat[bc/CC][bc%CC][threadIdx.x] = red[threadIdx.x][0];
}

// ============ kernel 2: SE MLP + GroupNorm fold into weights ============
__global__ void k_prep(const float* __restrict__ se_w1, const float* __restrict__ se_w2,
                       const float* __restrict__ gamma, const float* __restrict__ beta,
                       const float* __restrict__ wq, const float* __restrict__ bq,
                       const float* __restrict__ wk, const float* __restrict__ bk,
                       const float* __restrict__ wv, const float* __restrict__ bv) {
    int b = blockIdx.x;
    int c = threadIdx.x;
    __shared__ float sy[CC], sh[RR], sA[3][CC], sBc[3][CC];
    float st[6], stp[6];
    #pragma unroll
    for (int k=0;k<6;k++) st[k] = g_stat[b][c][k];
    int cp = c ^ 1;
    #pragma unroll
    for (int k=0;k<6;k++) stp[k] = g_stat[b][cp][k];

    sy[c] = st[4] * (1.0f/NN);
    __syncthreads();
    if (c < RR) {
        float h = 0.f;
        for (int ci=0; ci<CC; ci++) h += se_w1[c*CC+ci]*sy[ci];
        sh[c] = fmaxf(h, 0.f);
    }
    __syncthreads();
    {
        float z = 0.f;
        #pragma unroll
        for (int r=0;r<RR;r++) z += se_w2[c*RR+r]*sh[r];
        g_se[b][c] = 1.f/(1.f+fexp(-z));
    }
    const float inv = 1.0f/(2.0f*NN);
    float ga = gamma[c], be = beta[c];
    #pragma unroll
    for (int t=0;t<3;t++) {
        float mean = (st[2*t]+stp[2*t])*inv;
        float var  = (st[2*t+1]+stp[2*t+1])*inv - mean*mean;
        float rs = rsqrtf(var + EPSF);
        float A = rs*ga;
        sA[t][c] = A;
        sBc[t][c] = be - mean*A;
    }
    __syncthreads();
    for (int p=0;p<5;p++) {
        const float* w  = (p==0||p==2)? wq : (p==1||p==3)? wk : wv;
        const float* bb = (p==0||p==2)? bq : (p==1||p==3)? bk : bv;
        int t = (p<2)?0 : (p<4)?1 : 2;
        float acc = bb[c];
        for (int ci=0; ci<CC; ci++) {
            float wvl = w[c*CC+ci];
            acc += wvl * sBc[t][ci];
            g_W[p][b][ci][c] = wvl * sA[t][ci];
        }
        g_bias[p][b][c] = acc;
    }
}

// ====== kernel 3: projections -> fp16 operand tensors ======
__global__ void __launch_bounds__(256) k_proj(const float* __restrict__ x1,
                                              const float* __restrict__ x2) {
    int nt = blockIdx.x, p = blockIdx.y, b = blockIdx.z;
    int n0 = nt * 64;
    __shared__ float xs[CC][64];
    __shared__ float Wt[CC][CC];
    __shared__ float bias[CC];
    int tid = threadIdx.x;
    const float* s1 = x1 + (size_t)b*CC*NN + n0;
    const float* s2 = x2 + (size_t)b*CC*NN + n0;
    for (int idx = tid; idx < CC*64; idx += 256) {
        int ci = idx >> 6, n = idx & 63;
        float v;
        if (p < 2)       v = s1[(size_t)ci*NN + n];
        else if (p < 4)  v = s2[(size_t)ci*NN + n];
        else             v = s1[(size_t)ci*NN + n] + s2[(size_t)ci*NN + n];
        xs[ci][n] = v;
    }
    for (int idx = tid; idx < CC*CC; idx += 256)
        (&Wt[0][0])[idx] = (&g_W[p][b][0][0])[idx];
    if (tid < CC) bias[tid] = g_bias[p][b][tid];
    __syncthreads();

    int cg = tid >> 4;
    int ng = tid & 15;
    float acc[4][4];
    #pragma unroll
    for (int i=0;i<4;i++){ float bv_ = bias[4*cg+i];
        #pragma unroll
        for (int j=0;j<4;j++) acc[i][j]=bv_; }
    for (int ci=0; ci<CC; ci++) {
        float4 w4 = *(const float4*)&Wt[ci][4*cg];
        float4 x4 = *(const float4*)&xs[ci][4*ng];
        float wa[4]={w4.x,w4.y,w4.z,w4.w};
        float xa[4]={x4.x,x4.y,x4.z,x4.w};
        #pragma unroll
        for (int i=0;i<4;i++)
            #pragma unroll
            for (int j=0;j<4;j++) acc[i][j] += wa[i]*xa[j];
    }
    if (p == 0 || p == 2) {
        int br = p >> 1;
        #pragma unroll
        for (int j=0;j<4;j++) {
            int n = n0 + 4*ng + j;
            float v0=acc[0][j]*FSCALE, v1=acc[1][j]*FSCALE;
            float v2=acc[2][j]*FSCALE, v3=acc[3][j]*FSCALE;
            uint32_t h01 = packh2(v0, v1), h23 = packh2(v2, v3);
            float r0 = __half2float(__ushort_as_half((unsigned short)(h01 & 0xffff)));
            float r1 = __half2float(__ushort_as_half((unsigned short)(h01 >> 16)));
            float r2 = __half2float(__ushort_as_half((unsigned short)(h23 & 0xffff)));
            float r3 = __half2float(__ushort_as_half((unsigned short)(h23 >> 16)));
            uint32_t l01 = packh2(v0 - r0, v1 - r1), l23 = packh2(v2 - r2, v3 - r3);
            *(uint2*)&g_qh[br][b][n][4*cg] = make_uint2(h01, h23);
            *(uint2*)&g_ql[br][b][n][4*cg] = make_uint2(l01, l23);
        }
    } else if (p == 1 || p == 3) {
        int br = p >> 1;
        #pragma unroll
        for (int j=0;j<4;j++) {
            int n = n0 + 4*ng + j;
            uint32_t h01 = packh2(acc[0][j], acc[1][j]);
            uint32_t h23 = packh2(acc[2][j], acc[3][j]);
            *(uint2*)&g_k[br][b][n][4*cg] = make_uint2(h01, h23);
        }
    } else {
        #pragma unroll
        for (int i=0;i<4;i++) {
            int c = 4*cg + i;
            uint32_t h01 = packh2(acc[i][0], acc[i][1]);
            uint32_t h23 = packh2(acc[i][2], acc[i][3]);
            *(uint2*)&g_v[b][c][n0 + 4*ng] = make_uint2(h01, h23);
        }
    }
}

// ============== kernel 4: mma.sync flash attention (fp16, P single) ==============
// 128 thr / 4 warps; warp w owns q rows [16w,16w+16). Double-buffered K|V tiles
// streamed by cp.async. S = (Qh+Ql)K with widened dependency gaps; P single
// fp16 (linear error averages out); O += P V.
__global__ void __launch_bounds__(128, 4) k_attn() {
    __shared__ __align__(128) char smem[32768];   // 2 x (K 8KB | V 8KB)
    uint32_t sb = smem_u32(smem);
    int tid = threadIdx.x, l = tid & 31, w = tid >> 5;
    int qt = blockIdx.x;
    int bbi = blockIdx.y; int b = bbi >> 1, br = bbi & 1;

    const __half* QH = &g_qh[br][b][qt*64][0];
    const __half* QL = &g_ql[br][b][qt*64][0];
    const __half* K  = &g_k[br][b][0][0];
    const __half* V  = &g_v[b][0][0];

    // ---- Q tile into buf0 (plain), ldmatrix to regs ----
    for (int u = tid; u < 512; u += 128) {
        int r = u >> 3, q = u & 7;
        uint32_t off = SWZ(r*128 + q*16);
        *(uint4*)(smem + off)        = ((const uint4*)(QH + r*64))[q];
        *(uint4*)(smem + 8192 + off) = ((const uint4*)(QL + r*64))[q];
    }
    __syncthreads();
    uint32_t qh[4][4], ql[4][4];
    {
        int arow = 16*w + ((l>>3)&1)*8 + (l&7);
        int acolh = ((l>>4)&1)*16;
        #pragma unroll
        for (int ks = 0; ks < 4; ks++) {
            uint32_t off = SWZ(arow*128 + ks*32 + acolh);
            ldmx4(qh[ks], sb + off);
            ldmx4(ql[ks], sb + 8192 + off);
        }
    }
    __syncthreads();

    // ---- preload tiles 0 and 1 ----
    #pragma unroll
    for (int pre = 0; pre < 2; pre++) {
        uint32_t base = sb + pre*16384;
        const __half* kg = K + (size_t)pre*64*CC;
        const __half* vg = V + pre*64;
        for (int u = tid; u < 512; u += 128) {
            int r = u >> 3, q = u & 7;
            uint32_t off = SWZ(r*128 + q*16);
            CP_A16(base + off,        kg + r*64 + q*8);
            CP_A16(base + 8192 + off, vg + (size_t)r*NN + q*8);
        }
        CP_COMMIT();
    }

    float o[8][4];
    #pragma unroll
    for (int u=0;u<8;u++) { o[u][0]=0.f; o[u][1]=0.f; o[u][2]=0.f; o[u][3]=0.f; }
    float ls0 = 0.f, ls1 = 0.f;

    int brow = ((l>>4)&1)*8 + (l&7);
    int bcolh = ((l>>3)&1)*16;

    for (int kt = 0; kt < 64; kt++) {
        if (kt == 63) { CP_WAIT(0); } else { CP_WAIT(1); }
        __syncthreads();
        uint32_t base = sb + (kt&1)*16384;
        // ---- S = Qh*K then Ql*K (8-slot dependency gap on accumulators) ----
        float sc[8][4];
        #pragma unroll
        for (int u=0;u<8;u++) { sc[u][0]=0.f; sc[u][1]=0.f; sc[u][2]=0.f; sc[u][3]=0.f; }
        #pragma unroll
        for (int ks = 0; ks < 4; ks++) {
            uint32_t kf[4][4];
            #pragma unroll
            for (int up = 0; up < 4; up++)
                ldmx4(kf[up], base + SWZ((16*up + brow)*128 + ks*32 + bcolh));
            #pragma unroll
            for (int up = 0; up < 4; up++) {
                mma16816(sc[2*up],   qh[ks], kf[up][0], kf[up][1]);
                mma16816(sc[2*up+1], qh[ks], kf[up][2], kf[up][3]);
            }
            #pragma unroll
            for (int up = 0; up < 4; up++) {
                mma16816(sc[2*up],   ql[ks], kf[up][0], kf[up][1]);
                mma16816(sc[2*up+1], ql[ks], kf[up][2], kf[up][3]);
            }
        }
        // ---- softmax (exp2 domain), P single fp16 ----
        uint32_t ph[8][2];
        #pragma unroll
        for (int u = 0; u < 8; u++) {
            float p0 = fexp2(sc[u][0]), p1 = fexp2(sc[u][1]);
            float p2 = fexp2(sc[u][2]), p3 = fexp2(sc[u][3]);
            ls0 += p0 + p1; ls1 += p2 + p3;
            ph[u][0] = packh2(p0, p1);
            ph[u][1] = packh2(p2, p3);
        }
        // ---- O += P*V ----
        #pragma unroll
        for (int t = 0; t < 4; t++) {
            uint32_t ah[4] = { ph[2*t][0], ph[2*t][1], ph[2*t+1][0], ph[2*t+1][1] };
            uint32_t vf[4][4];
            #pragma unroll
            for (int up = 0; up < 4; up++)
                ldmx4(vf[up], base + 8192 + SWZ((16*up + brow)*128 + t*32 + bcolh));
            #pragma unroll
            for (int up = 0; up < 4; up++) {
                mma16816(o[2*up],   ah, vf[up][0], vf[up][1]);
                mma16816(o[2*up+1], ah, vf[up][2], vf[up][3]);
            }
        }
        __syncthreads();     // all warps done reading buf[kt&1]
        if (kt < 62) {       // stream tile kt+2 into the freed buffer
            int nt2 = kt + 2;
            const __half* kg = K + (size_t)nt2*64*CC;
            const __half* vg = V + nt2*64;
            for (int u = tid; u < 512; u += 128) {
                int r = u >> 3, q = u & 7;
                uint32_t off = SWZ(r*128 + q*16);
                CP_A16(base + off,        kg + r*64 + q*8);
                CP_A16(base + 8192 + off, vg + (size_t)r*NN + q*8);
            }
            CP_COMMIT();
        }
    }
    // ---- row sums across the quad, normalize ----
    ls0 += __shfl_xor_sync(0xffffffffu, ls0, 1);
    ls0 += __shfl_xor_sync(0xffffffffu, ls0, 2);
    ls1 += __shfl_xor_sync(0xffffffffu, ls1, 1);
    ls1 += __shfl_xor_sync(0xffffffffu, ls1, 2);
    float ri0 = 1.0f / ls0, ri1 = 1.0f / ls1;
    #pragma unroll
    for (int u=0;u<8;u++) { o[u][0]*=ri0; o[u][1]*=ri0; o[u][2]*=ri1; o[u][3]*=ri1; }
    // ---- transpose 16x64 -> [c][n] via smem, write g_h ----
    __syncthreads();
    float* W = (float*)smem + w * 1088;          // 64 rows x stride 17
    #pragma unroll
    for (int u = 0; u < 8; u++) {
        int c0 = 8*u + 2*(l&3);
        int r  = l >> 2;
        W[c0*17 + r]       = o[u][0];
        W[(c0+1)*17 + r]   = o[u][1];
        W[c0*17 + r + 8]   = o[u][2];
        W[(c0+1)*17 + r+8] = o[u][3];
    }
    __syncwarp();
    float* H = &g_h[br][b][0][0];
    int n0 = qt*64 + w*16;
    #pragma unroll
    for (int rep = 0; rep < 2; rep++) {
        int cc = 2*l + rep;
        #pragma unroll
        for (int k4 = 0; k4 < 4; k4++) {
            float4 v = make_float4(W[cc*17+4*k4], W[cc*17+4*k4+1],
                                   W[cc*17+4*k4+2], W[cc*17+4*k4+3]);
            *(float4*)&H[(size_t)cc*NN + n0 + 4*k4] = v;
        }
    }
}

// ================= kernel 5: final combine =================
__global__ void k_final(const float* __restrict__ x1, const float* __restrict__ x2,
                        float* __restrict__ out) {
    int idx4 = blockIdx.x*256 + threadIdx.x;
    if (idx4 >= BB*CC*NN/4) return;
    int idx = idx4 * 4;
    int bc = idx >> 12;
    int b = bc >> 6, c = bc & 63;
    float se = g_se[b][c];
    float4 a1 = *(const float4*)&x1[idx];
    float4 a2 = *(const float4*)&x2[idx];
    float4 h1 = *(const float4*)(&g_h[0][0][0][0] + idx);
    float4 h2 = *(const float4*)(&g_h[1][0][0][0] + idx);
    float xs[4] = {a1.x+a2.x, a1.y+a2.y, a1.z+a2.z, a1.w+a2.w};
    float h1a[4]={h1.x,h1.y,h1.z,h1.w};
    float h2a[4]={h2.x,h2.y,h2.z,h2.w};
    float oa[4];
    #pragma unroll
    for (int k=0;k<4;k++) {
        float ww = 1.f/(1.f+fexp(-xs[k]*se));
        oa[k] = 2.f*h1a[k]*ww + 2.f*h2a[k]*(1.f-ww);
    }
    *(float4*)&out[idx] = make_float4(oa[0],oa[1],oa[2],oa[3]);
}

// ================= launcher =================
extern "C" void kernel_launch(void* const* d_in, const int* in_sizes, int n_in,
                              void* d_out, int out_size) {
    const float* x1    = (const float*)d_in[0];
    const float* x2    = (const float*)d_in[1];
    const float* se_w1 = (const float*)d_in[2];
    const float* se_w2 = (const float*)d_in[3];
    const float* gam   = (const float*)d_in[4];
    const float* bet   = (const float*)d_in[5];
    const float* wq    = (const float*)d_in[6];
    const float* bq    = (const float*)d_in[7];
    const float* wk    = (const float*)d_in[8];
    const float* bk    = (const float*)d_in[9];
    const float* wv    = (const float*)d_in[10];
    const float* bv    = (const float*)d_in[11];
    float* out = (float*)d_out;

    k_stats<<<BB*CC, 256>>>(x1, x2);
    k_prep<<<BB, CC>>>(se_w1, se_w2, gam, bet, wq, bq, wk, bk, wv, bv);
    k_proj<<<dim3(64, 5, BB), 256>>>(x1, x2);
    k_attn<<<dim3(64, 8), 128>>>();
    k_final<<<(BB*CC*NN/4 + 255)/256, 256>>>(x1, x2, out);
}

// round 12
// speedup vs baseline: 1.4902x; 1.1920x over previous
#include <cuda_runtime.h>
#include <cuda_fp16.h>
#include <math.h>
#include <stdint.h>

#define BB 4
#define CC 64
#define NN 4096
#define RR 4
#define EPSF 1e-6f
#define FSCALE 0.18033688011112042f   // 0.125 * log2(e), folded into Q

typedef unsigned long long u64;

// ---------------- helpers ----------------
__device__ __forceinline__ uint32_t smem_u32(const void* p) {
    uint32_t a;
    asm("{ .reg .u64 t; cvta.to.shared.u64 t, %1; cvt.u32.u64 %0, t; }" : "=r"(a) : "l"(p));
    return a;
}
#define SWZ(off) ((off) ^ (((off) >> 3) & 0x70))   // SW128-style row swizzle

__device__ __forceinline__ void ldmx4(uint32_t* r, uint32_t addr) {
    asm volatile("ldmatrix.sync.aligned.m8n8.x4.shared.b16 {%0,%1,%2,%3}, [%4];"
        : "=r"(r[0]), "=r"(r[1]), "=r"(r[2]), "=r"(r[3]) : "r"(addr));
}
__device__ __forceinline__ void mma16816(float* d, const uint32_t* a,
                                         uint32_t b0, uint32_t b1) {
    asm volatile("mma.sync.aligned.m16n8k16.row.col.f32.f16.f16.f32 "
        "{%0,%1,%2,%3}, {%4,%5,%6,%7}, {%8,%9}, {%0,%1,%2,%3};"
        : "+f"(d[0]), "+f"(d[1]), "+f"(d[2]), "+f"(d[3])
        : "r"(a[0]), "r"(a[1]), "r"(a[2]), "r"(a[3]), "r"(b0), "r"(b1));
}
__device__ __forceinline__ uint32_t packh2(float lo, float hi) {  // lower=lo, upper=hi
    uint32_t r; asm("cvt.rn.f16x2.f32 %0, %1, %2;" : "=r"(r) : "f"(hi), "f"(lo)); return r;
}
#define CP_A16(dst, src) \
    asm volatile("cp.async.cg.shared.global [%0], [%1], 16;" :: "r"(dst), "l"(src) : "memory")
#define CP_COMMIT() asm volatile("cp.async.commit_group;" ::: "memory")
#define CP_WAIT(n)  asm volatile("cp.async.wait_group %0;" :: "n"(n) : "memory")

// ---- packed f32x2 (FFMA2 path) ----
__device__ __forceinline__ u64 pk2f(float lo, float hi) {
    u64 r; asm("mov.b64 %0, {%1,%2};" : "=l"(r) : "f"(lo), "f"(hi)); return r;
}
__device__ __forceinline__ void upk2f(u64 v, float& lo, float& hi) {
    asm("mov.b64 {%0,%1}, %2;" : "=f"(lo), "=f"(hi) : "l"(v));
}
__device__ __forceinline__ void upk2u(u64 v, uint32_t& lo, uint32_t& hi) {
    asm("mov.b64 {%0,%1}, %2;" : "=r"(lo), "=r"(hi) : "l"(v));
}
__device__ __forceinline__ u64 add2(u64 a, u64 b) {
    u64 d; asm("add.rn.f32x2 %0, %1, %2;" : "=l"(d) : "l"(a), "l"(b)); return d;
}
__device__ __forceinline__ u64 ffma2(u64 a, u64 b, u64 c) {
    u64 d; asm("fma.rn.f32x2 %0, %1, %2, %3;" : "=l"(d) : "l"(a), "l"(b), "l"(c)); return d;
}
// packed 2^x for two lanes (no clamp: args are O(±3) here)
__device__ __forceinline__ void exp2x2(float a, float b, float& ra, float& rb) {
    const float MG = 12582912.0f;
    u64 M2   = pk2f(MG, MG);
    u64 NM2  = pk2f(-MG, -MG);
    u64 NEG1 = pk2f(-1.0f, -1.0f);
    u64 x  = pk2f(a, b);
    u64 nf = add2(x, M2);
    u64 t  = add2(nf, NM2);          // nf - magic
    u64 f  = ffma2(t, NEG1, x);      // x - t, f in [-0.5,0.5]
    u64 p  = pk2f(1.3333558146e-3f, 1.3333558146e-3f);
    p = ffma2(p, f, pk2f(9.6181298421e-3f, 9.6181298421e-3f));
    p = ffma2(p, f, pk2f(5.5504108665e-2f, 5.5504108665e-2f));
    p = ffma2(p, f, pk2f(2.4022650696e-1f, 2.4022650696e-1f));
    p = ffma2(p, f, pk2f(6.9314718056e-1f, 6.9314718056e-1f));
    p = ffma2(p, f, pk2f(1.0f, 1.0f));
    uint32_t plo, phi, nlo, nhi;
    upk2u(p, plo, phi); upk2u(nf, nlo, nhi);
    ra = __int_as_float((int)plo + (int)(nlo << 23));
    rb = __int_as_float((int)phi + (int)(nhi << 23));
}

// scalar FMA-pipe exp (sigmoids)
__device__ __forceinline__ float fexp2s(float x) {
    const float MAGIC = 12582912.0f;
    x = fmaxf(x, -80.0f);
    float nf = x + MAGIC;
    float f  = x - (nf - MAGIC);
    float p = 1.3333558146e-3f;
    p = fmaf(p, f, 9.6181298421e-3f);
    p = fmaf(p, f, 5.5504108665e-2f);
    p = fmaf(p, f, 2.4022650696e-1f);
    p = fmaf(p, f, 6.9314718056e-1f);
    p = fmaf(p, f, 1.0f);
    int r = __float_as_int(p) + (__float_as_int(nf) << 23);
    return __int_as_float(r);
}
__device__ __forceinline__ float fexp(float x) { return fexp2s(x * 1.4426950408889634f); }

// ---------------- scratch (device globals) ----------------
__device__ float g_stat[BB][CC][6];
__device__ float g_se[BB][CC];
__device__ float g_W[5][BB][CC][CC];
__device__ float g_bias[5][BB][CC];
__device__ __half g_q[2][BB][NN][CC];    // Q fp16, per branch, [n][c], scaled by FSCALE
__device__ __half g_k[2][BB][NN][CC];    // K fp16, [n][c]
__device__ __half g_v[BB][CC][NN];       // V fp16, [c][n]
__device__ float g_h[2][BB][CC][NN];     // attention outputs

// ================= kernel 1: per-(b,c) sums over HW =================
__global__ void k_stats(const float* __restrict__ x1, const float* __restrict__ x2) {
    int bc = blockIdx.x;
    const float* p1 = x1 + (size_t)bc * NN;
    const float* p2 = x2 + (size_t)bc * NN;
    float s1=0.f,q1=0.f,s2=0.f,q2=0.f,sx=0.f,qx=0.f;
    for (int i = threadIdx.x; i < NN; i += 256) {
        float a = p1[i], b_ = p2[i], s = a + b_;
        s1 += a; q1 += a*a; s2 += b_; q2 += b_*b_; sx += s; qx += s*s;
    }
    __shared__ float red[6][256];
    red[0][threadIdx.x]=s1; red[1][threadIdx.x]=q1; red[2][threadIdx.x]=s2;
    red[3][threadIdx.x]=q2; red[4][threadIdx.x]=sx; red[5][threadIdx.x]=qx;
    __syncthreads();
    for (int off=128; off>=1; off>>=1) {
        if (threadIdx.x < (unsigned)off) {
            #pragma unroll
            for (int k=0;k<6;k++) red[k][threadIdx.x] += red[k][threadIdx.x+off];
        }
        __syncthreads();
    }
    if (threadIdx.x < 6) g_stat[bc/CC][bc%CC][threadIdx.x] = red[threadIdx.x][0];
}

// ============ kernel 2: SE MLP + GroupNorm fold into weights ============
__global__ void k_prep(const float* __restrict__ se_w1, const float* __restrict__ se_w2,
                       const float* __restrict__ gamma, const float* __restrict__ beta,
                       const float* __restrict__ wq, const float* __restrict__ bq,
                       const float* __restrict__ wk, const float* __restrict__ bk,
                       const float* __restrict__ wv, const float* __restrict__ bv) {
    int b = blockIdx.x;
    int c = threadIdx.x;
    __shared__ float sy[CC], sh[RR], sA[3][CC], sBc[3][CC];
    float st[6], stp[6];
    #pragma unroll
    for (int k=0;k<6;k++) st[k] = g_stat[b][c][k];
    int cp = c ^ 1;
    #pragma unroll
    for (int k=0;k<6;k++) stp[k] = g_stat[b][cp][k];

    sy[c] = st[4] * (1.0f/NN);
    __syncthreads();
    if (c < RR) {
        float h = 0.f;
        for (int ci=0; ci<CC; ci++) h += se_w1[c*CC+ci]*sy[ci];
        sh[c] = fmaxf(h, 0.f);
    }
    __syncthreads();
    {
        float z = 0.f;
        #pragma unroll
        for (int r=0;r<RR;r++) z += se_w2[c*RR+r]*sh[r];
        g_se[b][c] = 1.f/(1.f+fexp(-z));
    }
    const float inv = 1.0f/(2.0f*NN);
    float ga = gamma[c], be = beta[c];
    #pragma unroll
    for (int t=0;t<3;t++) {
        float mean = (st[2*t]+stp[2*t])*inv;
        float var  = (st[2*t+1]+stp[2*t+1])*inv - mean*mean;
        float rs = rsqrtf(var + EPSF);
        float A = rs*ga;
        sA[t][c] = A;
        sBc[t][c] = be - mean*A;
    }
    __syncthreads();
    for (int p=0;p<5;p++) {
        const float* w  = (p==0||p==2)? wq : (p==1||p==3)? wk : wv;
        const float* bb = (p==0||p==2)? bq : (p==1||p==3)? bk : bv;
        int t = (p<2)?0 : (p<4)?1 : 2;
        float acc = bb[c];
        for (int ci=0; ci<CC; ci++) {
            float wvl = w[c*CC+ci];
            acc += wvl * sBc[t][ci];
            g_W[p][b][ci][c] = wvl * sA[t][ci];
        }
        g_bias[p][b][c] = acc;
    }
}

// ====== kernel 3: projections -> fp16 operand tensors ======
__global__ void __launch_bounds__(256) k_proj(const float* __restrict__ x1,
                                              const float* __restrict__ x2) {
    int nt = blockIdx.x, p = blockIdx.y, b = blockIdx.z;
    int n0 = nt * 64;
    __shared__ float xs[CC][64];
    __shared__ float Wt[CC][CC];
    __shared__ float bias[CC];
    int tid = threadIdx.x;
    const float* s1 = x1 + (size_t)b*CC*NN + n0;
    const float* s2 = x2 + (size_t)b*CC*NN + n0;
    for (int idx = tid; idx < CC*64; idx += 256) {
        int ci = idx >> 6, n = idx & 63;
        float v;
        if (p < 2)       v = s1[(size_t)ci*NN + n];
        else if (p < 4)  v = s2[(size_t)ci*NN + n];
        else             v = s1[(size_t)ci*NN + n] + s2[(size_t)ci*NN + n];
        xs[ci][n] = v;
    }
    for (int idx = tid; idx < CC*CC; idx += 256)
        (&Wt[0][0])[idx] = (&g_W[p][b][0][0])[idx];
    if (tid < CC) bias[tid] = g_bias[p][b][tid];
    __syncthreads();

    int cg = tid >> 4;
    int ng = tid & 15;
    float acc[4][4];
    #pragma unroll
    for (int i=0;i<4;i++){ float bv_ = bias[4*cg+i];
        #pragma unroll
        for (int j=0;j<4;j++) acc[i][j]=bv_; }
    for (int ci=0; ci<CC; ci++) {
        float4 w4 = *(const float4*)&Wt[ci][4*cg];
        float4 x4 = *(const float4*)&xs[ci][4*ng];
        float wa[4]={w4.x,w4.y,w4.z,w4.w};
        float xa[4]={x4.x,x4.y,x4.z,x4.w};
        #pragma unroll
        for (int i=0;i<4;i++)
            #pragma unroll
            for (int j=0;j<4;j++) acc[i][j] += wa[i]*xa[j];
    }
    if (p == 0 || p == 2) {
        int br = p >> 1;
        #pragma unroll
        for (int j=0;j<4;j++) {
            int n = n0 + 4*ng + j;
            uint32_t h01 = packh2(acc[0][j]*FSCALE, acc[1][j]*FSCALE);
            uint32_t h23 = packh2(acc[2][j]*FSCALE, acc[3][j]*FSCALE);
            *(uint2*)&g_q[br][b][n][4*cg] = make_uint2(h01, h23);
        }
    } else if (p == 1 || p == 3) {
        int br = p >> 1;
        #pragma unroll
        for (int j=0;j<4;j++) {
            int n = n0 + 4*ng + j;
            uint32_t h01 = packh2(acc[0][j], acc[1][j]);
            uint32_t h23 = packh2(acc[2][j], acc[3][j]);
            *(uint2*)&g_k[br][b][n][4*cg] = make_uint2(h01, h23);
        }
    } else {
        #pragma unroll
        for (int i=0;i<4;i++) {
            int c = 4*cg + i;
            uint32_t h01 = packh2(acc[i][0], acc[i][1]);
            uint32_t h23 = packh2(acc[i][2], acc[i][3]);
            *(uint2*)&g_v[b][c][n0 + 4*ng] = make_uint2(h01, h23);
        }
    }
}

// ============== kernel 4: mma.sync flash attention (all-fp16 single) ==============
// 128 thr / 4 warps; warp w owns q rows [16w,16w+16). 3-stage K|V ring streamed
// by cp.async, ONE __syncthreads per kt; S = Q*K (single), packed-f32x2 softmax,
// O += P*V. 64 HMMA per warp-kt.
#define STG 16384
__global__ void __launch_bounds__(128, 4) k_attn() {
    __shared__ __align__(128) char smem[49152];   // 3 x (K 8KB | V 8KB)
    uint32_t sb = smem_u32(smem);
    int tid = threadIdx.x, l = tid & 31, w = tid >> 5;
    int qt = blockIdx.x;
    int bbi = blockIdx.y; int b = bbi >> 1, br = bbi & 1;

    const __half* Q = &g_q[br][b][qt*64][0];
    const __half* K = &g_k[br][b][0][0];
    const __half* V = &g_v[b][0][0];

    // ---- Q tile into stage0, ldmatrix to regs ----
    for (int u = tid; u < 512; u += 128) {
        int r = u >> 3, q = u & 7;
        *(uint4*)(smem + SWZ(r*128 + q*16)) = ((const uint4*)(Q + r*64))[q];
    }
    __syncthreads();
    uint32_t qh[4][4];
    {
        int arow = 16*w + ((l>>3)&1)*8 + (l&7);
        int acolh = ((l>>4)&1)*16;
        #pragma unroll
        for (int ks = 0; ks < 4; ks++)
            ldmx4(qh[ks], sb + SWZ(arow*128 + ks*32 + acolh));
    }
    __syncthreads();

    // ---- per-thread hoisted cp.async offsets ----
    uint32_t soff[4]; int gK[4]; size_t gV[4];
    {
        int rt = tid >> 3, q = tid & 7;
        #pragma unroll
        for (int i = 0; i < 4; i++) {
            int r = rt + 16*i;
            soff[i] = SWZ(r*128 + q*16);
            gK[i] = r*64 + q*8;
            gV[i] = (size_t)r*NN + q*8;
        }
    }
    // ---- preload tiles 0 and 1 ----
    #pragma unroll
    for (int pre = 0; pre < 2; pre++) {
        uint32_t base = sb + pre*STG;
        const __half* kg = K + (size_t)pre*64*CC;
        const __half* vg = V + pre*64;
        #pragma unroll
        for (int i = 0; i < 4; i++) {
            CP_A16(base + soff[i],        kg + gK[i]);
            CP_A16(base + 8192 + soff[i], vg + gV[i]);
        }
        CP_COMMIT();
    }

    float o[8][4];
    #pragma unroll
    for (int u=0;u<8;u++) { o[u][0]=0.f; o[u][1]=0.f; o[u][2]=0.f; o[u][3]=0.f; }
    u64 lsA = 0, lsB = 0;     // packed row-sum accumulators (cols 0/1 and 2/3)

    int brow = ((l>>4)&1)*8 + (l&7);
    int bcolh = ((l>>3)&1)*16;

    int stage = 0;
    for (int kt = 0; kt < 64; kt++) {
        if (kt == 63) { CP_WAIT(0); } else { CP_WAIT(1); }
        __syncthreads();               // stage kt ready; all warps done with kt-1
        uint32_t base = sb + stage*STG;
        if (kt < 62) {                 // prefetch kt+2 into stage last read at kt-1
            int ps = stage + 2; if (ps >= 3) ps -= 3;
            uint32_t pbase = sb + ps*STG;
            const __half* kg = K + (size_t)(kt+2)*64*CC;
            const __half* vg = V + (kt+2)*64;
            #pragma unroll
            for (int i = 0; i < 4; i++) {
                CP_A16(pbase + soff[i],        kg + gK[i]);
                CP_A16(pbase + 8192 + soff[i], vg + gV[i]);
            }
            CP_COMMIT();
        }
        // ---- S = Q*K ----
        float sc[8][4];
        #pragma unroll
        for (int u=0;u<8;u++) { sc[u][0]=0.f; sc[u][1]=0.f; sc[u][2]=0.f; sc[u][3]=0.f; }
        #pragma unroll
        for (int ks = 0; ks < 4; ks++) {
            uint32_t kf[4][4];
            #pragma unroll
            for (int up = 0; up < 4; up++)
                ldmx4(kf[up], base + SWZ((16*up + brow)*128 + ks*32 + bcolh));
            #pragma unroll
            for (int up = 0; up < 4; up++) {
                mma16816(sc[2*up],   qh[ks], kf[up][0], kf[up][1]);
                mma16816(sc[2*up+1], qh[ks], kf[up][2], kf[up][3]);
            }
        }
        // ---- softmax (exp2 domain, packed f32x2), P fp16 ----
        uint32_t ph[8][2];
        #pragma unroll
        for (int u = 0; u < 8; u++) {
            float p0, p1, p2, p3;
            exp2x2(sc[u][0], sc[u][1], p0, p1);
            exp2x2(sc[u][2], sc[u][3], p2, p3);
            lsA = add2(lsA, pk2f(p0, p1));
            lsB = add2(lsB, pk2f(p2, p3));
            ph[u][0] = packh2(p0, p1);
            ph[u][1] = packh2(p2, p3);
        }
        // ---- O += P*V ----
        #pragma unroll
        for (int t = 0; t < 4; t++) {
            uint32_t ah[4] = { ph[2*t][0], ph[2*t][1], ph[2*t+1][0], ph[2*t+1][1] };
            uint32_t vf[4][4];
            #pragma unroll
            for (int up = 0; up < 4; up++)
                ldmx4(vf[up], base + 8192 + SWZ((16*up + brow)*128 + t*32 + bcolh));
            #pragma unroll
            for (int up = 0; up < 4; up++) {
                mma16816(o[2*up],   ah, vf[up][0], vf[up][1]);
                mma16816(o[2*up+1], ah, vf[up][2], vf[up][3]);
            }
        }
        if (++stage == 3) stage = 0;
    }
    // ---- row sums across the quad, normalize ----
    float ls0, ls1, tA, tB;
    upk2f(lsA, ls0, tA); ls0 += tA;
    upk2f(lsB, ls1, tB); ls1 += tB;
    ls0 += __shfl_xor_sync(0xffffffffu, ls0, 1);
    ls0 += __shfl_xor_sync(0xffffffffu, ls0, 2);
    ls1 += __shfl_xor_sync(0xffffffffu, ls1, 1);
    ls1 += __shfl_xor_sync(0xffffffffu, ls1, 2);
    float ri0 = 1.0f / ls0, ri1 = 1.0f / ls1;
    #pragma unroll
    for (int u=0;u<8;u++) { o[u][0]*=ri0; o[u][1]*=ri0; o[u][2]*=ri1; o[u][3]*=ri1; }
    // ---- transpose 16x64 -> [c][n] via smem, write g_h ----
    __syncthreads();
    float* W = (float*)smem + w * 1088;          // 64 rows x stride 17
    #pragma unroll
    for (int u = 0; u < 8; u++) {
        int c0 = 8*u + 2*(l&3);
        int r  = l >> 2;
        W[c0*17 + r]       = o[u][0];
        W[(c0+1)*17 + r]   = o[u][1];
        W[c0*17 + r + 8]   = o[u][2];
        W[(c0+1)*17 + r+8] = o[u][3];
    }
    __syncwarp();
    float* H = &g_h[br][b][0][0];
    int n0 = qt*64 + w*16;
    #pragma unroll
    for (int rep = 0; rep < 2; rep++) {
        int cc = 2*l + rep;
        #pragma unroll
        for (int k4 = 0; k4 < 4; k4++) {
            float4 v = make_float4(W[cc*17+4*k4], W[cc*17+4*k4+1],
                                   W[cc*17+4*k4+2], W[cc*17+4*k4+3]);
            *(float4*)&H[(size_t)cc*NN + n0 + 4*k4] = v;
        }
    }
}

// ================= kernel 5: final combine =================
__global__ void k_final(const float* __restrict__ x1, const float* __restrict__ x2,
                        float* __restrict__ out) {
    int idx4 = blockIdx.x*256 + threadIdx.x;
    if (idx4 >= BB*CC*NN/4) return;
    int idx = idx4 * 4;
    int bc = idx >> 12;
    int b = bc >> 6, c = bc & 63;
    float se = g_se[b][c];
    float4 a1 = *(const float4*)&x1[idx];
    float4 a2 = *(const float4*)&x2[idx];
    float4 h1 = *(const float4*)(&g_h[0][0][0][0] + idx);
    float4 h2 = *(const float4*)(&g_h[1][0][0][0] + idx);
    float xs[4] = {a1.x+a2.x, a1.y+a2.y, a1.z+a2.z, a1.w+a2.w};
    float h1a[4]={h1.x,h1.y,h1.z,h1.w};
    float h2a[4]={h2.x,h2.y,h2.z,h2.w};
    float oa[4];
    #pragma unroll
    for (int k=0;k<4;k++) {
        float ww = 1.f/(1.f+fexp(-xs[k]*se));
        oa[k] = 2.f*h1a[k]*ww + 2.f*h2a[k]*(1.f-ww);
    }
    *(float4*)&out[idx] = make_float4(oa[0],oa[1],oa[2],oa[3]);
}

// ================= launcher =================
extern "C" void kernel_launch(void* const* d_in, const int* in_sizes, int n_in,
                              void* d_out, int out_size) {
    const float* x1    = (const float*)d_in[0];
    const float* x2    = (const float*)d_in[1];
    const float* se_w1 = (const float*)d_in[2];
    const float* se_w2 = (const float*)d_in[3];
    const float* gam   = (const float*)d_in[4];
    const float* bet   = (const float*)d_in[5];
    const float* wq    = (const float*)d_in[6];
    const float* bq    = (const float*)d_in[7];
    const float* wk    = (const float*)d_in[8];
    const float* bk    = (const float*)d_in[9];
    const float* wv    = (const float*)d_in[10];
    const float* bv    = (const float*)d_in[11];
    float* out = (float*)d_out;

    k_stats<<<BB*CC, 256>>>(x1, x2);
    k_prep<<<BB, CC>>>(se_w1, se_w2, gam, bet, wq, bq, wk, bk, wv, bv);
    k_proj<<<dim3(64, 5, BB), 256>>>(x1, x2);
    k_attn<<<dim3(64, 8), 128>>>();
    k_final<<<(BB*CC*NN/4 + 255)/256, 256>>>(x1, x2, out);
}

// round 13
// speedup vs baseline: 1.7742x; 1.1906x over previous
#include <cuda_runtime.h>
#include <cuda_fp16.h>
#include <math.h>
#include <stdint.h>

#define BB 4
#define CC 64
#define NN 4096
#define RR 4
#define EPSF 1e-6f
#define FSCALE 0.18033688011112042f   // 0.125 * log2(e), folded into Q

typedef unsigned long long u64;

// ---------------- helpers ----------------
__device__ __forceinline__ uint32_t smem_u32(const void* p) {
    uint32_t a;
    asm("{ .reg .u64 t; cvta.to.shared.u64 t, %1; cvt.u32.u64 %0, t; }" : "=r"(a) : "l"(p));
    return a;
}
#define SWZ(off) ((off) ^ (((off) >> 3) & 0x70))   // SW128-style row swizzle

__device__ __forceinline__ void ldmx4(uint32_t* r, uint32_t addr) {
    asm volatile("ldmatrix.sync.aligned.m8n8.x4.shared.b16 {%0,%1,%2,%3}, [%4];"
        : "=r"(r[0]), "=r"(r[1]), "=r"(r[2]), "=r"(r[3]) : "r"(addr));
}
__device__ __forceinline__ void mma16816(float* d, const uint32_t* a,
                                         uint32_t b0, uint32_t b1) {
    asm volatile("mma.sync.aligned.m16n8k16.row.col.f32.f16.f16.f32 "
        "{%0,%1,%2,%3}, {%4,%5,%6,%7}, {%8,%9}, {%0,%1,%2,%3};"
        : "+f"(d[0]), "+f"(d[1]), "+f"(d[2]), "+f"(d[3])
        : "r"(a[0]), "r"(a[1]), "r"(a[2]), "r"(a[3]), "r"(b0), "r"(b1));
}
__device__ __forceinline__ uint32_t packh2(float lo, float hi) {  // lower=lo, upper=hi
    uint32_t r; asm("cvt.rn.f16x2.f32 %0, %1, %2;" : "=r"(r) : "f"(hi), "f"(lo)); return r;
}
#define CP_A16(dst, src) \
    asm volatile("cp.async.cg.shared.global [%0], [%1], 16;" :: "r"(dst), "l"(src) : "memory")
#define CP_COMMIT() asm volatile("cp.async.commit_group;" ::: "memory")
#define CP_WAIT(n)  asm volatile("cp.async.wait_group %0;" :: "n"(n) : "memory")

// ---- packed f32x2 row-sum accumulation ----
__device__ __forceinline__ u64 pk2f(float lo, float hi) {
    u64 r; asm("mov.b64 %0, {%1,%2};" : "=l"(r) : "f"(lo), "f"(hi)); return r;
}
__device__ __forceinline__ void upk2f(u64 v, float& lo, float& hi) {
    asm("mov.b64 {%0,%1}, %2;" : "=f"(lo), "=f"(hi) : "l"(v));
}
__device__ __forceinline__ u64 add2(u64 a, u64 b) {
    u64 d; asm("add.rn.f32x2 %0, %1, %2;" : "=l"(d) : "l"(a), "l"(b)); return d;
}
// MUFU exp2 — 1 issue slot per exp, runs on the otherwise-idle MUFU pipe
__device__ __forceinline__ float ex2f(float x) {
    float r; asm("ex2.approx.f32 %0, %1;" : "=f"(r) : "f"(x)); return r;
}

// scalar FMA-pipe exp (sigmoids, outside hot loop)
__device__ __forceinline__ float fexp2s(float x) {
    const float MAGIC = 12582912.0f;
    x = fmaxf(x, -80.0f);
    float nf = x + MAGIC;
    float f  = x - (nf - MAGIC);
    float p = 1.3333558146e-3f;
    p = fmaf(p, f, 9.6181298421e-3f);
    p = fmaf(p, f, 5.5504108665e-2f);
    p = fmaf(p, f, 2.4022650696e-1f);
    p = fmaf(p, f, 6.9314718056e-1f);
    p = fmaf(p, f, 1.0f);
    int r = __float_as_int(p) + (__float_as_int(nf) << 23);
    return __int_as_float(r);
}
__device__ __forceinline__ float fexp(float x) { return fexp2s(x * 1.4426950408889634f); }

// ---------------- scratch (device globals) ----------------
__device__ float g_stat[BB][CC][6];
__device__ float g_se[BB][CC];
__device__ float g_W[5][BB][CC][CC];
__device__ float g_bias[5][BB][CC];
__device__ __half g_q[2][BB][NN][CC];    // Q fp16, per branch, [n][c], scaled by FSCALE
__device__ __half g_k[2][BB][NN][CC];    // K fp16, [n][c]
__device__ __half g_v[BB][CC][NN];       // V fp16, [c][n]
__device__ float g_h[2][BB][CC][NN];     // attention outputs

// ================= kernel 1: per-(b,c) sums over HW =================
__global__ void k_stats(const float* __restrict__ x1, const float* __restrict__ x2) {
    int bc = blockIdx.x;
    const float* p1 = x1 + (size_t)bc * NN;
    const float* p2 = x2 + (size_t)bc * NN;
    float s1=0.f,q1=0.f,s2=0.f,q2=0.f,sx=0.f,qx=0.f;
    for (int i = threadIdx.x; i < NN; i += 256) {
        float a = p1[i], b_ = p2[i], s = a + b_;
        s1 += a; q1 += a*a; s2 += b_; q2 += b_*b_; sx += s; qx += s*s;
    }
    __shared__ float red[6][256];
    red[0][threadIdx.x]=s1; red[1][threadIdx.x]=q1; red[2][threadIdx.x]=s2;
    red[3][threadIdx.x]=q2; red[4][threadIdx.x]=sx; red[5][threadIdx.x]=qx;
    __syncthreads();
    for (int off=128; off>=1; off>>=1) {
        if (threadIdx.x < (unsigned)off) {
            #pragma unroll
            for (int k=0;k<6;k++) red[k][threadIdx.x] += red[k][threadIdx.x+off];
        }
        __syncthreads();
    }
    if (threadIdx.x < 6) g_stat[bc/CC][bc%CC][threadIdx.x] = red[threadIdx.x][0];
}

// ============ kernel 2: SE MLP + GroupNorm fold into weights ============
__global__ void k_prep(const float* __restrict__ se_w1, const float* __restrict__ se_w2,
                       const float* __restrict__ gamma, const float* __restrict__ beta,
                       const float* __restrict__ wq, const float* __restrict__ bq,
                       const float* __restrict__ wk, const float* __restrict__ bk,
                       const float* __restrict__ wv, const float* __restrict__ bv) {
    int b = blockIdx.x;
    int c = threadIdx.x;
    __shared__ float sy[CC], sh[RR], sA[3][CC], sBc[3][CC];
    float st[6], stp[6];
    #pragma unroll
    for (int k=0;k<6;k++) st[k] = g_stat[b][c][k];
    int cp = c ^ 1;
    #pragma unroll
    for (int k=0;k<6;k++) stp[k] = g_stat[b][cp][k];

    sy[c] = st[4] * (1.0f/NN);
    __syncthreads();
    if (c < RR) {
        float h = 0.f;
        for (int ci=0; ci<CC; ci++) h += se_w1[c*CC+ci]*sy[ci];
        sh[c] = fmaxf(h, 0.f);
    }
    __syncthreads();
    {
        float z = 0.f;
        #pragma unroll
        for (int r=0;r<RR;r++) z += se_w2[c*RR+r]*sh[r];
        g_se[b][c] = 1.f/(1.f+fexp(-z));
    }
    const float inv = 1.0f/(2.0f*NN);
    float ga = gamma[c], be = beta[c];
    #pragma unroll
    for (int t=0;t<3;t++) {
        float mean = (st[2*t]+stp[2*t])*inv;
        float var  = (st[2*t+1]+stp[2*t+1])*inv - mean*mean;
        float rs = rsqrtf(var + EPSF);
        float A = rs*ga;
        sA[t][c] = A;
        sBc[t][c] = be - mean*A;
    }
    __syncthreads();
    for (int p=0;p<5;p++) {
        const float* w  = (p==0||p==2)? wq : (p==1||p==3)? wk : wv;
        const float* bb = (p==0||p==2)? bq : (p==1||p==3)? bk : bv;
        int t = (p<2)?0 : (p<4)?1 : 2;
        float acc = bb[c];
        for (int ci=0; ci<CC; ci++) {
            float wvl = w[c*CC+ci];
            acc += wvl * sBc[t][ci];
            g_W[p][b][ci][c] = wvl * sA[t][ci];
        }
        g_bias[p][b][c] = acc;
    }
}

// ====== kernel 3: projections -> fp16 operand tensors ======
__global__ void __launch_bounds__(256) k_proj(const float* __restrict__ x1,
                                              const float* __restrict__ x2) {
    int nt = blockIdx.x, p = blockIdx.y, b = blockIdx.z;
    int n0 = nt * 64;
    __shared__ float xs[CC][64];
    __shared__ float Wt[CC][CC];
    __shared__ float bias[CC];
    int tid = threadIdx.x;
    const float* s1 = x1 + (size_t)b*CC*NN + n0;
    const float* s2 = x2 + (size_t)b*CC*NN + n0;
    for (int idx = tid; idx < CC*64; idx += 256) {
        int ci = idx >> 6, n = idx & 63;
        float v;
        if (p < 2)       v = s1[(size_t)ci*NN + n];
        else if (p < 4)  v = s2[(size_t)ci*NN + n];
        else             v = s1[(size_t)ci*NN + n] + s2[(size_t)ci*NN + n];
        xs[ci][n] = v;
    }
    for (int idx = tid; idx < CC*CC; idx += 256)
        (&Wt[0][0])[idx] = (&g_W[p][b][0][0])[idx];
    if (tid < CC) bias[tid] = g_bias[p][b][tid];
    __syncthreads();

    int cg = tid >> 4;
    int ng = tid & 15;
    float acc[4][4];
    #pragma unroll
    for (int i=0;i<4;i++){ float bv_ = bias[4*cg+i];
        #pragma unroll
        for (int j=0;j<4;j++) acc[i][j]=bv_; }
    for (int ci=0; ci<CC; ci++) {
        float4 w4 = *(const float4*)&Wt[ci][4*cg];
        float4 x4 = *(const float4*)&xs[ci][4*ng];
        float wa[4]={w4.x,w4.y,w4.z,w4.w};
        float xa[4]={x4.x,x4.y,x4.z,x4.w};
        #pragma unroll
        for (int i=0;i<4;i++)
            #pragma unroll
            for (int j=0;j<4;j++) acc[i][j] += wa[i]*xa[j];
    }
    if (p == 0 || p == 2) {
        int br = p >> 1;
        #pragma unroll
        for (int j=0;j<4;j++) {
            int n = n0 + 4*ng + j;
            uint32_t h01 = packh2(acc[0][j]*FSCALE, acc[1][j]*FSCALE);
            uint32_t h23 = packh2(acc[2][j]*FSCALE, acc[3][j]*FSCALE);
            *(uint2*)&g_q[br][b][n][4*cg] = make_uint2(h01, h23);
        }
    } else if (p == 1 || p == 3) {
        int br = p >> 1;
        #pragma unroll
        for (int j=0;j<4;j++) {
            int n = n0 + 4*ng + j;
            uint32_t h01 = packh2(acc[0][j], acc[1][j]);
            uint32_t h23 = packh2(acc[2][j], acc[3][j]);
            *(uint2*)&g_k[br][b][n][4*cg] = make_uint2(h01, h23);
        }
    } else {
        #pragma unroll
        for (int i=0;i<4;i++) {
            int c = 4*cg + i;
            uint32_t h01 = packh2(acc[i][0], acc[i][1]);
            uint32_t h23 = packh2(acc[i][2], acc[i][3]);
            *(uint2*)&g_v[b][c][n0 + 4*ng] = make_uint2(h01, h23);
        }
    }
}

// ============== kernel 4: mma.sync flash attention (fp16, MUFU softmax) ==============
// 128 thr / 4 warps; warp w owns q rows [16w,16w+16). 3-stage K|V ring streamed
// by cp.async, ONE __syncthreads per kt; S = Q*K, exp via ex2.approx (MUFU pipe,
// 1 slot/exp), O += P*V. 64 HMMA per warp-kt.
#define STG 16384
__global__ void __launch_bounds__(128, 4) k_attn() {
    __shared__ __align__(128) char smem[49152];   // 3 x (K 8KB | V 8KB)
    uint32_t sb = smem_u32(smem);
    int tid = threadIdx.x, l = tid & 31, w = tid >> 5;
    int qt = blockIdx.x;
    int bbi = blockIdx.y; int b = bbi >> 1, br = bbi & 1;

    const __half* Q = &g_q[br][b][qt*64][0];
    const __half* K = &g_k[br][b][0][0];
    const __half* V = &g_v[b][0][0];

    // ---- Q tile into stage0, ldmatrix to regs ----
    for (int u = tid; u < 512; u += 128) {
        int r = u >> 3, q = u & 7;
        *(uint4*)(smem + SWZ(r*128 + q*16)) = ((const uint4*)(Q + r*64))[q];
    }
    __syncthreads();
    uint32_t qh[4][4];
    {
        int arow = 16*w + ((l>>3)&1)*8 + (l&7);
        int acolh = ((l>>4)&1)*16;
        #pragma unroll
        for (int ks = 0; ks < 4; ks++)
            ldmx4(qh[ks], sb + SWZ(arow*128 + ks*32 + acolh));
    }
    __syncthreads();

    // ---- per-thread hoisted cp.async offsets ----
    uint32_t soff[4]; int gK[4]; size_t gV[4];
    {
        int rt = tid >> 3, q = tid & 7;
        #pragma unroll
        for (int i = 0; i < 4; i++) {
            int r = rt + 16*i;
            soff[i] = SWZ(r*128 + q*16);
            gK[i] = r*64 + q*8;
            gV[i] = (size_t)r*NN + q*8;
        }
    }
    // ---- preload tiles 0 and 1 ----
    #pragma unroll
    for (int pre = 0; pre < 2; pre++) {
        uint32_t base = sb + pre*STG;
        const __half* kg = K + (size_t)pre*64*CC;
        const __half* vg = V + pre*64;
        #pragma unroll
        for (int i = 0; i < 4; i++) {
            CP_A16(base + soff[i],        kg + gK[i]);
            CP_A16(base + 8192 + soff[i], vg + gV[i]);
        }
        CP_COMMIT();
    }

    float o[8][4];
    #pragma unroll
    for (int u=0;u<8;u++) { o[u][0]=0.f; o[u][1]=0.f; o[u][2]=0.f; o[u][3]=0.f; }
    u64 lsA = 0, lsB = 0;     // packed row-sum accumulators (cols 0/1 and 2/3)

    int brow = ((l>>4)&1)*8 + (l&7);
    int bcolh = ((l>>3)&1)*16;

    int stage = 0;
    for (int kt = 0; kt < 64; kt++) {
        if (kt == 63) { CP_WAIT(0); } else { CP_WAIT(1); }
        __syncthreads();               // stage kt ready; all warps done with kt-1
        uint32_t base = sb + stage*STG;
        if (kt < 62) {                 // prefetch kt+2 into stage last read at kt-1
            int ps = stage + 2; if (ps >= 3) ps -= 3;
            uint32_t pbase = sb + ps*STG;
            const __half* kg = K + (size_t)(kt+2)*64*CC;
            const __half* vg = V + (kt+2)*64;
            #pragma unroll
            for (int i = 0; i < 4; i++) {
                CP_A16(pbase + soff[i],        kg + gK[i]);
                CP_A16(pbase + 8192 + soff[i], vg + gV[i]);
            }
            CP_COMMIT();
        }
        // ---- S = Q*K ----
        float sc[8][4];
        #pragma unroll
        for (int u=0;u<8;u++) { sc[u][0]=0.f; sc[u][1]=0.f; sc[u][2]=0.f; sc[u][3]=0.f; }
        #pragma unroll
        for (int ks = 0; ks < 4; ks++) {
            uint32_t kf[4][4];
            #pragma unroll
            for (int up = 0; up < 4; up++)
                ldmx4(kf[up], base + SWZ((16*up + brow)*128 + ks*32 + bcolh));
            #pragma unroll
            for (int up = 0; up < 4; up++) {
                mma16816(sc[2*up],   qh[ks], kf[up][0], kf[up][1]);
                mma16816(sc[2*up+1], qh[ks], kf[up][2], kf[up][3]);
            }
        }
        // ---- softmax: exp2 on MUFU pipe (1 slot/exp), P fp16 ----
        uint32_t ph[8][2];
        #pragma unroll
        for (int u = 0; u < 8; u++) {
            float p0 = ex2f(sc[u][0]), p1 = ex2f(sc[u][1]);
            float p2 = ex2f(sc[u][2]), p3 = ex2f(sc[u][3]);
            lsA = add2(lsA, pk2f(p0, p1));
            lsB = add2(lsB, pk2f(p2, p3));
            ph[u][0] = packh2(p0, p1);
            ph[u][1] = packh2(p2, p3);
        }
        // ---- O += P*V ----
        #pragma unroll
        for (int t = 0; t < 4; t++) {
            uint32_t ah[4] = { ph[2*t][0], ph[2*t][1], ph[2*t+1][0], ph[2*t+1][1] };
            uint32_t vf[4][4];
            #pragma unroll
            for (int up = 0; up < 4; up++)
                ldmx4(vf[up], base + 8192 + SWZ((16*up + brow)*128 + t*32 + bcolh));
            #pragma unroll
            for (int up = 0; up < 4; up++) {
                mma16816(o[2*up],   ah, vf[up][0], vf[up][1]);
                mma16816(o[2*up+1], ah, vf[up][2], vf[up][3]);
            }
        }
        if (++stage == 3) stage = 0;
    }
    // ---- row sums across the quad, normalize ----
    float ls0, ls1, tA, tB;
    upk2f(lsA, ls0, tA); ls0 += tA;
    upk2f(lsB, ls1, tB); ls1 += tB;
    ls0 += __shfl_xor_sync(0xffffffffu, ls0, 1);
    ls0 += __shfl_xor_sync(0xffffffffu, ls0, 2);
    ls1 += __shfl_xor_sync(0xffffffffu, ls1, 1);
    ls1 += __shfl_xor_sync(0xffffffffu, ls1, 2);
    float ri0 = 1.0f / ls0, ri1 = 1.0f / ls1;
    #pragma unroll
    for (int u=0;u<8;u++) { o[u][0]*=ri0; o[u][1]*=ri0; o[u][2]*=ri1; o[u][3]*=ri1; }
    // ---- transpose 16x64 -> [c][n] via smem, write g_h ----
    __syncthreads();
    float* W = (float*)smem + w * 1088;          // 64 rows x stride 17
    #pragma unroll
    for (int u = 0; u < 8; u++) {
        int c0 = 8*u + 2*(l&3);
        int r  = l >> 2;
        W[c0*17 + r]       = o[u][0];
        W[(c0+1)*17 + r]   = o[u][1];
        W[c0*17 + r + 8]   = o[u][2];
        W[(c0+1)*17 + r+8] = o[u][3];
    }
    __syncwarp();
    float* H = &g_h[br][b][0][0];
    int n0 = qt*64 + w*16;
    #pragma unroll
    for (int rep = 0; rep < 2; rep++) {
        int cc = 2*l + rep;
        #pragma unroll
        for (int k4 = 0; k4 < 4; k4++) {
            float4 v = make_float4(W[cc*17+4*k4], W[cc*17+4*k4+1],
                                   W[cc*17+4*k4+2], W[cc*17+4*k4+3]);
            *(float4*)&H[(size_t)cc*NN + n0 + 4*k4] = v;
        }
    }
}

// ================= kernel 5: final combine =================
__global__ void k_final(const float* __restrict__ x1, const float* __restrict__ x2,
                        float* __restrict__ out) {
    int idx4 = blockIdx.x*256 + threadIdx.x;
    if (idx4 >= BB*CC*NN/4) return;
    int idx = idx4 * 4;
    int bc = idx >> 12;
    int b = bc >> 6, c = bc & 63;
    float se = g_se[b][c];
    float4 a1 = *(const float4*)&x1[idx];
    float4 a2 = *(const float4*)&x2[idx];
    float4 h1 = *(const float4*)(&g_h[0][0][0][0] + idx);
    float4 h2 = *(const float4*)(&g_h[1][0][0][0] + idx);
    float xs[4] = {a1.x+a2.x, a1.y+a2.y, a1.z+a2.z, a1.w+a2.w};
    float h1a[4]={h1.x,h1.y,h1.z,h1.w};
    float h2a[4]={h2.x,h2.y,h2.z,h2.w};
    float oa[4];
    #pragma unroll
    for (int k=0;k<4;k++) {
        float ww = 1.f/(1.f+fexp(-xs[k]*se));
        oa[k] = 2.f*h1a[k]*ww + 2.f*h2a[k]*(1.f-ww);
    }
    *(float4*)&out[idx] = make_float4(oa[0],oa[1],oa[2],oa[3]);
}

// ================= launcher =================
extern "C" void kernel_launch(void* const* d_in, const int* in_sizes, int n_in,
                              void* d_out, int out_size) {
    const float* x1    = (const float*)d_in[0];
    const float* x2    = (const float*)d_in[1];
    const float* se_w1 = (const float*)d_in[2];
    const float* se_w2 = (const float*)d_in[3];
    const float* gam   = (const float*)d_in[4];
    const float* bet   = (const float*)d_in[5];
    const float* wq    = (const float*)d_in[6];
    const float* bq    = (const float*)d_in[7];
    const float* wk    = (const float*)d_in[8];
    const float* bk    = (const float*)d_in[9];
    const float* wv    = (const float*)d_in[10];
    const float* bv    = (const float*)d_in[11];
    float* out = (float*)d_out;

    k_stats<<<BB*CC, 256>>>(x1, x2);
    k_prep<<<BB, CC>>>(se_w1, se_w2, gam, bet, wq, bq, wk, bk, wv, bv);
    k_proj<<<dim3(64, 5, BB), 256>>>(x1, x2);
    k_attn<<<dim3(64, 8), 128>>>();
    k_final<<<(BB*CC*NN/4 + 255)/256, 256>>>(x1, x2, out);
}

// round 14
// speedup vs baseline: 1.9525x; 1.1005x over previous
#include <cuda_runtime.h>
#include <cuda_fp16.h>
#include <math.h>
#include <stdint.h>

#define BB 4
#define CC 64
#define NN 4096
#define RR 4
#define EPSF 1e-6f
#define FSCALE 0.18033688011112042f   // 0.125 * log2(e), folded into Q

typedef unsigned long long u64;

// ---------------- helpers ----------------
__device__ __forceinline__ uint32_t smem_u32(const void* p) {
    uint32_t a;
    asm("{ .reg .u64 t; cvta.to.shared.u64 t, %1; cvt.u32.u64 %0, t; }" : "=r"(a) : "l"(p));
    return a;
}
#define SWZ(off) ((off) ^ (((off) >> 3) & 0x70))   // SW128-style row swizzle

__device__ __forceinline__ void ldmx4(uint32_t* r, uint32_t addr) {
    asm volatile("ldmatrix.sync.aligned.m8n8.x4.shared.b16 {%0,%1,%2,%3}, [%4];"
        : "=r"(r[0]), "=r"(r[1]), "=r"(r[2]), "=r"(r[3]) : "r"(addr));
}
__device__ __forceinline__ void mma16816(float* d, const uint32_t* a,
                                         uint32_t b0, uint32_t b1) {
    asm volatile("mma.sync.aligned.m16n8k16.row.col.f32.f16.f16.f32 "
        "{%0,%1,%2,%3}, {%4,%5,%6,%7}, {%8,%9}, {%0,%1,%2,%3};"
        : "+f"(d[0]), "+f"(d[1]), "+f"(d[2]), "+f"(d[3])
        : "r"(a[0]), "r"(a[1]), "r"(a[2]), "r"(a[3]), "r"(b0), "r"(b1));
}
__device__ __forceinline__ uint32_t packh2(float lo, float hi) {  // lower=lo, upper=hi
    uint32_t r; asm("cvt.rn.f16x2.f32 %0, %1, %2;" : "=r"(r) : "f"(hi), "f"(lo)); return r;
}
#define CP_A16(dst, src) \
    asm volatile("cp.async.cg.shared.global [%0], [%1], 16;" :: "r"(dst), "l"(src) : "memory")
#define CP_COMMIT() asm volatile("cp.async.commit_group;" ::: "memory")
#define CP_WAIT(n)  asm volatile("cp.async.wait_group %0;" :: "n"(n) : "memory")

// ---- packed f32x2 ----
__device__ __forceinline__ u64 pk2f(float lo, float hi) {
    u64 r; asm("mov.b64 %0, {%1,%2};" : "=l"(r) : "f"(lo), "f"(hi)); return r;
}
__device__ __forceinline__ void upk2f(u64 v, float& lo, float& hi) {
    asm("mov.b64 {%0,%1}, %2;" : "=f"(lo), "=f"(hi) : "l"(v));
}
__device__ __forceinline__ u64 add2(u64 a, u64 b) {
    u64 d; asm("add.rn.f32x2 %0, %1, %2;" : "=l"(d) : "l"(a), "l"(b)); return d;
}
__device__ __forceinline__ u64 ffma2(u64 a, u64 b, u64 c) {
    u64 d; asm("fma.rn.f32x2 %0, %1, %2, %3;" : "=l"(d) : "l"(a), "l"(b), "l"(c)); return d;
}
// MUFU exp2 — 1 issue slot per exp
__device__ __forceinline__ float ex2f(float x) {
    float r; asm("ex2.approx.f32 %0, %1;" : "=f"(r) : "f"(x)); return r;
}

// scalar FMA-pipe exp (sigmoids, outside hot loop)
__device__ __forceinline__ float fexp2s(float x) {
    const float MAGIC = 12582912.0f;
    x = fmaxf(x, -80.0f);
    float nf = x + MAGIC;
    float f  = x - (nf - MAGIC);
    float p = 1.3333558146e-3f;
    p = fmaf(p, f, 9.6181298421e-3f);
    p = fmaf(p, f, 5.5504108665e-2f);
    p = fmaf(p, f, 2.4022650696e-1f);
    p = fmaf(p, f, 6.9314718056e-1f);
    p = fmaf(p, f, 1.0f);
    int r = __float_as_int(p) + (__float_as_int(nf) << 23);
    return __int_as_float(r);
}
__device__ __forceinline__ float fexp(float x) { return fexp2s(x * 1.4426950408889634f); }

// ---------------- scratch (device globals) ----------------
__device__ float g_stat[BB][CC][6];
__device__ float g_se[BB][CC];
__device__ float g_W[5][BB][CC][CC];
__device__ float g_bias[5][BB][CC];
__device__ __half g_q[2][BB][NN][CC];    // Q fp16, per branch, [n][c], scaled by FSCALE
__device__ __half g_k[2][BB][NN][CC];    // K fp16, [n][c]
__device__ __half g_v[BB][CC][NN];       // V fp16, [c][n]
__device__ float g_h[2][BB][CC][NN];     // attention outputs

// ================= kernel 1: per-(b,c) sums over HW =================
__global__ void k_stats(const float* __restrict__ x1, const float* __restrict__ x2) {
    int bc = blockIdx.x;
    const float* p1 = x1 + (size_t)bc * NN;
    const float* p2 = x2 + (size_t)bc * NN;
    float s1=0.f,q1=0.f,s2=0.f,q2=0.f,sx=0.f,qx=0.f;
    for (int i = threadIdx.x; i < NN; i += 256) {
        float a = p1[i], b_ = p2[i], s = a + b_;
        s1 += a; q1 += a*a; s2 += b_; q2 += b_*b_; sx += s; qx += s*s;
    }
    __shared__ float red[6][256];
    red[0][threadIdx.x]=s1; red[1][threadIdx.x]=q1; red[2][threadIdx.x]=s2;
    red[3][threadIdx.x]=q2; red[4][threadIdx.x]=sx; red[5][threadIdx.x]=qx;
    __syncthreads();
    for (int off=128; off>=1; off>>=1) {
        if (threadIdx.x < (unsigned)off) {
            #pragma unroll
            for (int k=0;k<6;k++) red[k][threadIdx.x] += red[k][threadIdx.x+off];
        }
        __syncthreads();
    }
    if (threadIdx.x < 6) g_stat[bc/CC][bc%CC][threadIdx.x] = red[threadIdx.x][0];
}

// ============ kernel 2: SE MLP + GroupNorm fold into weights ============
__global__ void k_prep(const float* __restrict__ se_w1, const float* __restrict__ se_w2,
                       const float* __restrict__ gamma, const float* __restrict__ beta,
                       const float* __restrict__ wq, const float* __restrict__ bq,
                       const float* __restrict__ wk, const float* __restrict__ bk,
                       const float* __restrict__ wv, const float* __restrict__ bv) {
    int b = blockIdx.x;
    int c = threadIdx.x;
    __shared__ float sy[CC], sh[RR], sA[3][CC], sBc[3][CC];
    float st[6], stp[6];
    #pragma unroll
    for (int k=0;k<6;k++) st[k] = g_stat[b][c][k];
    int cp = c ^ 1;
    #pragma unroll
    for (int k=0;k<6;k++) stp[k] = g_stat[b][cp][k];

    sy[c] = st[4] * (1.0f/NN);
    __syncthreads();
    if (c < RR) {
        float h = 0.f;
        for (int ci=0; ci<CC; ci++) h += se_w1[c*CC+ci]*sy[ci];
        sh[c] = fmaxf(h, 0.f);
    }
    __syncthreads();
    {
        float z = 0.f;
        #pragma unroll
        for (int r=0;r<RR;r++) z += se_w2[c*RR+r]*sh[r];
        g_se[b][c] = 1.f/(1.f+fexp(-z));
    }
    const float inv = 1.0f/(2.0f*NN);
    float ga = gamma[c], be = beta[c];
    #pragma unroll
    for (int t=0;t<3;t++) {
        float mean = (st[2*t]+stp[2*t])*inv;
        float var  = (st[2*t+1]+stp[2*t+1])*inv - mean*mean;
        float rs = rsqrtf(var + EPSF);
        float A = rs*ga;
        sA[t][c] = A;
        sBc[t][c] = be - mean*A;
    }
    __syncthreads();
    for (int p=0;p<5;p++) {
        const float* w  = (p==0||p==2)? wq : (p==1||p==3)? wk : wv;
        const float* bb = (p==0||p==2)? bq : (p==1||p==3)? bk : bv;
        int t = (p<2)?0 : (p<4)?1 : 2;
        float acc = bb[c];
        for (int ci=0; ci<CC; ci++) {
            float wvl = w[c*CC+ci];
            acc += wvl * sBc[t][ci];
            g_W[p][b][ci][c] = wvl * sA[t][ci];
        }
        g_bias[p][b][c] = acc;
    }
}

// ====== kernel 3: projections -> fp16 operand tensors (f32x2 inner loop) ======
__global__ void __launch_bounds__(256) k_proj(const float* __restrict__ x1,
                                              const float* __restrict__ x2) {
    int nt = blockIdx.x, p = blockIdx.y, b = blockIdx.z;
    int n0 = nt * 64;
    __shared__ float xs[CC][64];
    __shared__ float Wt[CC][CC];
    __shared__ float bias[CC];
    int tid = threadIdx.x;
    const float* s1 = x1 + (size_t)b*CC*NN + n0;
    const float* s2 = x2 + (size_t)b*CC*NN + n0;
    for (int idx = tid; idx < CC*64; idx += 256) {
        int ci = idx >> 6, n = idx & 63;
        float v;
        if (p < 2)       v = s1[(size_t)ci*NN + n];
        else if (p < 4)  v = s2[(size_t)ci*NN + n];
        else             v = s1[(size_t)ci*NN + n] + s2[(size_t)ci*NN + n];
        xs[ci][n] = v;
    }
    for (int idx = tid; idx < CC*CC; idx += 256)
        (&Wt[0][0])[idx] = (&g_W[p][b][0][0])[idx];
    if (tid < CC) bias[tid] = g_bias[p][b][tid];
    __syncthreads();

    int cg = tid >> 4;
    int ng = tid & 15;
    u64 acc2[4][2];
    #pragma unroll
    for (int i=0;i<4;i++){ float bv_ = bias[4*cg+i];
        acc2[i][0] = pk2f(bv_, bv_); acc2[i][1] = pk2f(bv_, bv_); }
    for (int ci=0; ci<CC; ci++) {
        float4 w4 = *(const float4*)&Wt[ci][4*cg];
        float4 x4 = *(const float4*)&xs[ci][4*ng];
        u64 x01 = pk2f(x4.x, x4.y), x23 = pk2f(x4.z, x4.w);
        float wa[4]={w4.x,w4.y,w4.z,w4.w};
        #pragma unroll
        for (int i=0;i<4;i++) {
            u64 wd = pk2f(wa[i], wa[i]);
            acc2[i][0] = ffma2(wd, x01, acc2[i][0]);
            acc2[i][1] = ffma2(wd, x23, acc2[i][1]);
        }
    }
    float acc[4][4];
    #pragma unroll
    for (int i=0;i<4;i++) {
        upk2f(acc2[i][0], acc[i][0], acc[i][1]);
        upk2f(acc2[i][1], acc[i][2], acc[i][3]);
    }
    if (p == 0 || p == 2) {
        int br = p >> 1;
        #pragma unroll
        for (int j=0;j<4;j++) {
            int n = n0 + 4*ng + j;
            uint32_t h01 = packh2(acc[0][j]*FSCALE, acc[1][j]*FSCALE);
            uint32_t h23 = packh2(acc[2][j]*FSCALE, acc[3][j]*FSCALE);
            *(uint2*)&g_q[br][b][n][4*cg] = make_uint2(h01, h23);
        }
    } else if (p == 1 || p == 3) {
        int br = p >> 1;
        #pragma unroll
        for (int j=0;j<4;j++) {
            int n = n0 + 4*ng + j;
            uint32_t h01 = packh2(acc[0][j], acc[1][j]);
            uint32_t h23 = packh2(acc[2][j], acc[3][j]);
            *(uint2*)&g_k[br][b][n][4*cg] = make_uint2(h01, h23);
        }
    } else {
        #pragma unroll
        for (int i=0;i<4;i++) {
            int c = 4*cg + i;
            uint32_t h01 = packh2(acc[i][0], acc[i][1]);
            uint32_t h23 = packh2(acc[i][2], acc[i][3]);
            *(uint2*)&g_v[b][c][n0 + 4*ng] = make_uint2(h01, h23);
        }
    }
}

// ============== kernel 4: mma.sync flash attention, M=32 per warp ==============
// 64 thr / 2 warps; warp w owns q rows [32w, 32w+32) as two 16-row groups that
// SHARE every K/V fragment -> LDSM bytes per FLOP halved. 3-stage cp.async ring,
// one __syncthreads per kt; MUFU softmax; 128 HMMA per warp-kt.
#define STG 16384
__global__ void __launch_bounds__(64, 4) k_attn() {
    __shared__ __align__(128) char smem[49152];   // 3 x (K 8KB | V 8KB)
    uint32_t sb = smem_u32(smem);
    int tid = threadIdx.x, l = tid & 31, w = tid >> 5;
    int qt = blockIdx.x;
    int bbi = blockIdx.y; int b = bbi >> 1, br = bbi & 1;

    const __half* Q = &g_q[br][b][qt*64][0];
    const __half* K = &g_k[br][b][0][0];
    const __half* V = &g_v[b][0][0];

    // ---- Q tile (64 rows) into stage0, ldmatrix to regs (2 groups/warp) ----
    for (int u = tid; u < 512; u += 64) {
        int r = u >> 3, q = u & 7;
        *(uint4*)(smem + SWZ(r*128 + q*16)) = ((const uint4*)(Q + r*64))[q];
    }
    __syncthreads();
    uint32_t qA[4][4], qB[4][4];
    {
        int arowA = 32*w + ((l>>3)&1)*8 + (l&7);
        int acolh = ((l>>4)&1)*16;
        #pragma unroll
        for (int ks = 0; ks < 4; ks++) {
            ldmx4(qA[ks], sb + SWZ(arowA*128 + ks*32 + acolh));
            ldmx4(qB[ks], sb + SWZ((arowA+16)*128 + ks*32 + acolh));
        }
    }
    __syncthreads();

    // ---- per-thread hoisted cp.async offsets (64 thr -> 8 rows each) ----
    uint32_t soff[8]; int gK[8]; size_t gV[8];
    {
        int rt = tid >> 3, q = tid & 7;
        #pragma unroll
        for (int i = 0; i < 8; i++) {
            int r = rt + 8*i;
            soff[i] = SWZ(r*128 + q*16);
            gK[i] = r*64 + q*8;
            gV[i] = (size_t)r*NN + q*8;
        }
    }
    // ---- preload tiles 0 and 1 ----
    #pragma unroll
    for (int pre = 0; pre < 2; pre++) {
        uint32_t base = sb + pre*STG;
        const __half* kg = K + (size_t)pre*64*CC;
        const __half* vg = V + pre*64;
        #pragma unroll
        for (int i = 0; i < 8; i++) {
            CP_A16(base + soff[i],        kg + gK[i]);
            CP_A16(base + 8192 + soff[i], vg + gV[i]);
        }
        CP_COMMIT();
    }

    float oA[8][4], oB[8][4];
    #pragma unroll
    for (int u=0;u<8;u++) {
        oA[u][0]=0.f; oA[u][1]=0.f; oA[u][2]=0.f; oA[u][3]=0.f;
        oB[u][0]=0.f; oB[u][1]=0.f; oB[u][2]=0.f; oB[u][3]=0.f;
    }
    u64 lsA0 = 0, lsA1 = 0, lsB0 = 0, lsB1 = 0;

    int brow = ((l>>4)&1)*8 + (l&7);
    int bcolh = ((l>>3)&1)*16;

    int stage = 0;
    for (int kt = 0; kt < 64; kt++) {
        if (kt == 63) { CP_WAIT(0); } else { CP_WAIT(1); }
        __syncthreads();               // stage kt ready; both warps done with kt-1
        uint32_t base = sb + stage*STG;
        if (kt < 62) {                 // prefetch kt+2 into stage last read at kt-1
            int ps = stage + 2; if (ps >= 3) ps -= 3;
            uint32_t pbase = sb + ps*STG;
            const __half* kg = K + (size_t)(kt+2)*64*CC;
            const __half* vg = V + (kt+2)*64;
            #pragma unroll
            for (int i = 0; i < 8; i++) {
                CP_A16(pbase + soff[i],        kg + gK[i]);
                CP_A16(pbase + 8192 + soff[i], vg + gV[i]);
            }
            CP_COMMIT();
        }
        // ---- S = Q*K for both row groups, sharing K fragments ----
        float scA[8][4], scB[8][4];
        #pragma unroll
        for (int u=0;u<8;u++) {
            scA[u][0]=0.f; scA[u][1]=0.f; scA[u][2]=0.f; scA[u][3]=0.f;
            scB[u][0]=0.f; scB[u][1]=0.f; scB[u][2]=0.f; scB[u][3]=0.f;
        }
        #pragma unroll
        for (int ks = 0; ks < 4; ks++) {
            uint32_t kf[4][4];
            #pragma unroll
            for (int up = 0; up < 4; up++)
                ldmx4(kf[up], base + SWZ((16*up + brow)*128 + ks*32 + bcolh));
            #pragma unroll
            for (int up = 0; up < 4; up++) {
                mma16816(scA[2*up],   qA[ks], kf[up][0], kf[up][1]);
                mma16816(scA[2*up+1], qA[ks], kf[up][2], kf[up][3]);
                mma16816(scB[2*up],   qB[ks], kf[up][0], kf[up][1]);
                mma16816(scB[2*up+1], qB[ks], kf[up][2], kf[up][3]);
            }
        }
        // ---- softmax: exp2 on MUFU pipe, P fp16 ----
        uint32_t phA[8][2], phB[8][2];
        #pragma unroll
        for (int u = 0; u < 8; u++) {
            float a0 = ex2f(scA[u][0]), a1 = ex2f(scA[u][1]);
            float a2 = ex2f(scA[u][2]), a3 = ex2f(scA[u][3]);
            lsA0 = add2(lsA0, pk2f(a0, a1));
            lsA1 = add2(lsA1, pk2f(a2, a3));
            phA[u][0] = packh2(a0, a1); phA[u][1] = packh2(a2, a3);
            float b0 = ex2f(scB[u][0]), b1 = ex2f(scB[u][1]);
            float b2 = ex2f(scB[u][2]), b3 = ex2f(scB[u][3]);
            lsB0 = add2(lsB0, pk2f(b0, b1));
            lsB1 = add2(lsB1, pk2f(b2, b3));
            phB[u][0] = packh2(b0, b1); phB[u][1] = packh2(b2, b3);
        }
        // ---- O += P*V for both groups, sharing V fragments ----
        #pragma unroll
        for (int t = 0; t < 4; t++) {
            uint32_t aA[4] = { phA[2*t][0], phA[2*t][1], phA[2*t+1][0], phA[2*t+1][1] };
            uint32_t aB[4] = { phB[2*t][0], phB[2*t][1], phB[2*t+1][0], phB[2*t+1][1] };
            uint32_t vf[4][4];
            #pragma unroll
            for (int up = 0; up < 4; up++)
                ldmx4(vf[up], base + 8192 + SWZ((16*up + brow)*128 + t*32 + bcolh));
            #pragma unroll
            for (int up = 0; up < 4; up++) {
                mma16816(oA[2*up],   aA, vf[up][0], vf[up][1]);
                mma16816(oA[2*up+1], aA, vf[up][2], vf[up][3]);
                mma16816(oB[2*up],   aB, vf[up][0], vf[up][1]);
                mma16816(oB[2*up+1], aB, vf[up][2], vf[up][3]);
            }
        }
        if (++stage == 3) stage = 0;
    }
    // ---- row sums across the quad, normalize ----
    {
        float s0, s1, t0, t1;
        upk2f(lsA0, s0, t0); s0 += t0;
        upk2f(lsA1, s1, t1); s1 += t1;
        s0 += __shfl_xor_sync(0xffffffffu, s0, 1);
        s0 += __shfl_xor_sync(0xffffffffu, s0, 2);
        s1 += __shfl_xor_sync(0xffffffffu, s1, 1);
        s1 += __shfl_xor_sync(0xffffffffu, s1, 2);
        float r0 = 1.0f/s0, r1 = 1.0f/s1;
        #pragma unroll
        for (int u=0;u<8;u++) { oA[u][0]*=r0; oA[u][1]*=r0; oA[u][2]*=r1; oA[u][3]*=r1; }
        upk2f(lsB0, s0, t0); s0 += t0;
        upk2f(lsB1, s1, t1); s1 += t1;
        s0 += __shfl_xor_sync(0xffffffffu, s0, 1);
        s0 += __shfl_xor_sync(0xffffffffu, s0, 2);
        s1 += __shfl_xor_sync(0xffffffffu, s1, 1);
        s1 += __shfl_xor_sync(0xffffffffu, s1, 2);
        r0 = 1.0f/s0; r1 = 1.0f/s1;
        #pragma unroll
        for (int u=0;u<8;u++) { oB[u][0]*=r0; oB[u][1]*=r0; oB[u][2]*=r1; oB[u][3]*=r1; }
    }
    // ---- transpose both groups via smem, write g_h ----
    __syncthreads();   // ring drained (CP_WAIT(0) done); smem reusable
    float* Wp = (float*)smem + w * 1088;         // 64 rows x stride 17 per warp
    float* H = &g_h[br][b][0][0];
    #pragma unroll
    for (int g = 0; g < 2; g++) {
        float (*og)[4] = g ? oB : oA;
        __syncwarp();
        #pragma unroll
        for (int u = 0; u < 8; u++) {
            int c0 = 8*u + 2*(l&3);
            int r  = l >> 2;
            Wp[c0*17 + r]       = og[u][0];
            Wp[(c0+1)*17 + r]   = og[u][1];
            Wp[c0*17 + r + 8]   = og[u][2];
            Wp[(c0+1)*17 + r+8] = og[u][3];
        }
        __syncwarp();
        int n0 = qt*64 + 32*w + 16*g;
        #pragma unroll
        for (int rep = 0; rep < 2; rep++) {
            int cc = 2*l + rep;
            #pragma unroll
            for (int k4 = 0; k4 < 4; k4++) {
                float4 v = make_float4(Wp[cc*17+4*k4], Wp[cc*17+4*k4+1],
                                       Wp[cc*17+4*k4+2], Wp[cc*17+4*k4+3]);
                *(float4*)&H[(size_t)cc*NN + n0 + 4*k4] = v;
            }
        }
    }
}

// ================= kernel 5: final combine =================
__global__ void k_final(const float* __restrict__ x1, const float* __restrict__ x2,
                        float* __restrict__ out) {
    int idx4 = blockIdx.x*256 + threadIdx.x;
    if (idx4 >= BB*CC*NN/4) return;
    int idx = idx4 * 4;
    int bc = idx >> 12;
    int b = bc >> 6, c = bc & 63;
    float se = g_se[b][c];
    float4 a1 = *(const float4*)&x1[idx];
    float4 a2 = *(const float4*)&x2[idx];
    float4 h1 = *(const float4*)(&g_h[0][0][0][0] + idx);
    float4 h2 = *(const float4*)(&g_h[1][0][0][0] + idx);
    float xs[4] = {a1.x+a2.x, a1.y+a2.y, a1.z+a2.z, a1.w+a2.w};
    float h1a[4]={h1.x,h1.y,h1.z,h1.w};
    float h2a[4]={h2.x,h2.y,h2.z,h2.w};
    float oa[4];
    #pragma unroll
    for (int k=0;k<4;k++) {
        float ww = 1.f/(1.f+fexp(-xs[k]*se));
        oa[k] = 2.f*h1a[k]*ww + 2.f*h2a[k]*(1.f-ww);
    }
    *(float4*)&out[idx] = make_float4(oa[0],oa[1],oa[2],oa[3]);
}

// ================= launcher =================
extern "C" void kernel_launch(void* const* d_in, const int* in_sizes, int n_in,
                              void* d_out, int out_size) {
    const float* x1    = (const float*)d_in[0];
    const float* x2    = (const float*)d_in[1];
    const float* se_w1 = (const float*)d_in[2];
    const float* se_w2 = (const float*)d_in[3];
    const float* gam   = (const float*)d_in[4];
    const float* bet   = (const float*)d_in[5];
    const float* wq    = (const float*)d_in[6];
    const float* bq    = (const float*)d_in[7];
    const float* wk    = (const float*)d_in[8];
    const float* bk    = (const float*)d_in[9];
    const float* wv    = (const float*)d_in[10];
    const float* bv    = (const float*)d_in[11];
    float* out = (float*)d_out;

    k_stats<<<BB*CC, 256>>>(x1, x2);
    k_prep<<<BB, CC>>>(se_w1, se_w2, gam, bet, wq, bq, wk, bk, wv, bv);
    k_proj<<<dim3(64, 5, BB), 256>>>(x1, x2);
    k_attn<<<dim3(64, 8), 64>>>();
    k_final<<<(BB*CC*NN/4 + 255)/256, 256>>>(x1, x2, out);
}